// round 1
// baseline (speedup 1.0000x reference)
#include <cuda_runtime.h>
#include <math.h>

// Problem dims (fixed by the reference)
#define BB   8
#define SEQ  2048
#define DIM  512

// Scratch (device globals: no allocation allowed in kernel_launch)
__device__ float g_Q[(size_t)BB * SEQ * DIM];
__device__ float g_K[(size_t)BB * SEQ * DIM];
__device__ float g_V[(size_t)BB * SEQ * DIM];
__device__ float g_S[(size_t)BB * SEQ * SEQ];

// ---------------------------------------------------------------------------
// Tiled fp32 GEMM.
//   C[m,n] = scale * sum_k A[m,k] * B'[.,.] (+ bias[n])
//   BTRANS=true : B is [N x K] row-major (C = A * B^T)   -> QKV proj, Q*K^T
//   BTRANS=false: B is [K x N] row-major (C = A * B)     -> attn * V
// Tile: 128 (M) x 64 (N) x 16 (K), 256 threads, 8x4 acc per thread.
// All dims are multiples of the tile sizes -> no bounds checks.
// ---------------------------------------------------------------------------
template <bool BTRANS>
__global__ __launch_bounds__(256) void gemm_tile(
    const float* __restrict__ A, const float* __restrict__ Bm,
    const float* __restrict__ bias, float* __restrict__ C,
    int lda, int ldb, int ldc,
    long strideA, long strideB, long strideC,
    int K, float scale)
{
    __shared__ float As[128 * 17];   // [m][k], stride 17 to avoid bank conflicts
    __shared__ float Bs[16 * 68];    // [k][n], stride 68 (16B-aligned, conflict-free LDS.128)

    const int bz = blockIdx.z;
    A  += (long)bz * strideA;
    Bm += (long)bz * strideB;
    C  += (long)bz * strideC;

    const int bm = blockIdx.y * 128;
    const int bn = blockIdx.x * 64;
    const int tid = threadIdx.x;
    const int tx = tid & 15;         // n direction (4 cols each)
    const int ty = tid >> 4;         // m direction (8 rows each)

    float acc[8][4];
#pragma unroll
    for (int i = 0; i < 8; i++)
#pragma unroll
        for (int j = 0; j < 4; j++) acc[i][j] = 0.f;

    for (int k0 = 0; k0 < K; k0 += 16) {
        // --- load A tile: 128x16 floats = 512 float4, 2 per thread ---
#pragma unroll
        for (int t = 0; t < 2; t++) {
            int f4  = tid + t * 256;           // 0..511
            int row = f4 >> 2;                 // 0..127
            int c4  = (f4 & 3) * 4;            // 0,4,8,12
            float4 v = *(const float4*)(A + (long)(bm + row) * lda + k0 + c4);
            float* p = &As[row * 17 + c4];
            p[0] = v.x; p[1] = v.y; p[2] = v.z; p[3] = v.w;
        }
        // --- load B tile into Bs[k][n] ---
        if (BTRANS) {
            // B is [N x K]: each thread loads 4 k's of one n, transposing
            int n  = tid >> 2;                 // 0..63
            int kq = (tid & 3) * 4;            // 0,4,8,12
            float4 v = *(const float4*)(Bm + (long)(bn + n) * ldb + k0 + kq);
            Bs[(kq + 0) * 68 + n] = v.x;
            Bs[(kq + 1) * 68 + n] = v.y;
            Bs[(kq + 2) * 68 + n] = v.z;
            Bs[(kq + 3) * 68 + n] = v.w;
        } else {
            // B is [K x N]: direct copy, one float4 per thread
            int kr = tid >> 4;                 // 0..15
            int n4 = (tid & 15) * 4;           // 0..60
            float4 v = *(const float4*)(Bm + (long)(k0 + kr) * ldb + bn + n4);
            float* p = &Bs[kr * 68 + n4];
            p[0] = v.x; p[1] = v.y; p[2] = v.z; p[3] = v.w;
        }
        __syncthreads();

#pragma unroll
        for (int kk = 0; kk < 16; kk++) {
            float a[8];
#pragma unroll
            for (int i = 0; i < 8; i++) a[i] = As[(ty * 8 + i) * 17 + kk];
            float4 b4 = *(const float4*)(&Bs[kk * 68 + tx * 4]);
            float b[4] = {b4.x, b4.y, b4.z, b4.w};
#pragma unroll
            for (int i = 0; i < 8; i++)
#pragma unroll
                for (int j = 0; j < 4; j++)
                    acc[i][j] += a[i] * b[j];
        }
        __syncthreads();
    }

    // --- epilogue ---
    const int col = bn + tx * 4;
    float4 bb = make_float4(0.f, 0.f, 0.f, 0.f);
    if (bias) bb = *(const float4*)(bias + col);
#pragma unroll
    for (int i = 0; i < 8; i++) {
        int row = bm + ty * 8 + i;
        float4 o;
        o.x = acc[i][0] * scale + bb.x;
        o.y = acc[i][1] * scale + bb.y;
        o.z = acc[i][2] * scale + bb.z;
        o.w = acc[i][3] * scale + bb.w;
        *(float4*)(C + (long)row * ldc + col) = o;
    }
}

// ---------------------------------------------------------------------------
// Row-wise masked softmax over the key axis. One block per (b, q) row.
// SEQ = 2048 = 256 threads * 8 values, held in registers.
// ---------------------------------------------------------------------------
__global__ __launch_bounds__(256) void softmax_kernel(
    float* __restrict__ S, const int* __restrict__ mask)
{
    const int row = blockIdx.x;            // 0 .. B*SEQ-1
    const int b   = row / SEQ;
    float* s = S + (size_t)row * SEQ;
    const int* m = mask + b * SEQ;

    float v[8];
    float mx = -3.0e38f;
#pragma unroll
    for (int t = 0; t < 8; t++) {
        int k = threadIdx.x + t * 256;
        float x = s[k];
        if (m[k] == 0) x = -1e9f;
        v[t] = x;
        mx = fmaxf(mx, x);
    }

    __shared__ float red[256];
    red[threadIdx.x] = mx;
    __syncthreads();
    for (int o = 128; o > 0; o >>= 1) {
        if (threadIdx.x < o)
            red[threadIdx.x] = fmaxf(red[threadIdx.x], red[threadIdx.x + o]);
        __syncthreads();
    }
    mx = red[0];
    __syncthreads();

    float sum = 0.f;
#pragma unroll
    for (int t = 0; t < 8; t++) {
        v[t] = __expf(v[t] - mx);
        sum += v[t];
    }
    red[threadIdx.x] = sum;
    __syncthreads();
    for (int o = 128; o > 0; o >>= 1) {
        if (threadIdx.x < o)
            red[threadIdx.x] += red[threadIdx.x + o];
        __syncthreads();
    }
    float inv = 1.f / red[0];
#pragma unroll
    for (int t = 0; t < 8; t++)
        s[threadIdx.x + t * 256] = v[t] * inv;
}

// ---------------------------------------------------------------------------
// Launch: QKV projections -> scores -> softmax -> AV
// ---------------------------------------------------------------------------
extern "C" void kernel_launch(void* const* d_in, const int* in_sizes, int n_in,
                              void* d_out, int out_size)
{
    const float* x    = (const float*)d_in[0];
    const int*   mask = (const int*)  d_in[1];
    const float* Wk   = (const float*)d_in[2];
    const float* bk   = (const float*)d_in[3];
    const float* Wq   = (const float*)d_in[4];
    const float* bq   = (const float*)d_in[5];
    const float* Wv   = (const float*)d_in[6];
    const float* bv   = (const float*)d_in[7];
    float* out = (float*)d_out;

    float *Q, *Kp, *V, *S;
    cudaGetSymbolAddress((void**)&Q,  g_Q);
    cudaGetSymbolAddress((void**)&Kp, g_K);
    cudaGetSymbolAddress((void**)&V,  g_V);
    cudaGetSymbolAddress((void**)&S,  g_S);

    dim3 blk(256);

    // QKV projections: [B*SEQ x DIM] = x[B*SEQ x DIM] * W^T + b
    dim3 gp(DIM / 64, (BB * SEQ) / 128, 1);
    gemm_tile<true><<<gp, blk>>>(x, Wq, bq, Q,  DIM, DIM, DIM, 0, 0, 0, DIM, 1.f);
    gemm_tile<true><<<gp, blk>>>(x, Wk, bk, Kp, DIM, DIM, DIM, 0, 0, 0, DIM, 1.f);
    gemm_tile<true><<<gp, blk>>>(x, Wv, bv, V,  DIM, DIM, DIM, 0, 0, 0, DIM, 1.f);

    // scores: S[b] = Q[b] * K[b]^T / sqrt(DIM)
    const float inv_sqrt_d = 0.044194173824159216f;  // 1/sqrt(512)
    dim3 gs(SEQ / 64, SEQ / 128, BB);
    gemm_tile<true><<<gs, blk>>>(Q, Kp, nullptr, S,
                                 DIM, DIM, SEQ,
                                 (long)SEQ * DIM, (long)SEQ * DIM, (long)SEQ * SEQ,
                                 DIM, inv_sqrt_d);

    // softmax over key axis, with mask
    softmax_kernel<<<BB * SEQ, 256>>>(S, mask);

    // out[b] = P[b] * V[b]
    dim3 ga(DIM / 64, SEQ / 128, BB);
    gemm_tile<false><<<ga, blk>>>(S, V, nullptr, out,
                                  SEQ, DIM, DIM,
                                  (long)SEQ * SEQ, (long)SEQ * DIM, (long)SEQ * DIM,
                                  SEQ, 1.f);
}

// round 6
// speedup vs baseline: 1.7676x; 1.7676x over previous
#include <cuda_runtime.h>
#include <cstdint>

#define BB   8
#define SEQ  2048
#define DIM  512

// Scratch (device globals; no allocs allowed)
__device__ float g_Q [(size_t)BB * SEQ * DIM];
__device__ float g_K [(size_t)BB * SEQ * DIM];
__device__ float g_V [(size_t)BB * SEQ * DIM];
__device__ float g_Vt[(size_t)BB * SEQ * DIM];
__device__ float g_S [(size_t)BB * SEQ * SEQ];

__device__ __forceinline__ uint32_t tf32cvt(float f) {
    uint32_t r; asm("cvt.rna.tf32.f32 %0, %1;" : "=r"(r) : "f"(f)); return r;
}

#define MMA_TF32(d, a, b) \
    asm volatile( \
        "mma.sync.aligned.m16n8k8.row.col.f32.tf32.tf32.f32 " \
        "{%0,%1,%2,%3}, {%4,%5,%6,%7}, {%8,%9}, {%0,%1,%2,%3};" \
        : "+f"((d)[0]), "+f"((d)[1]), "+f"((d)[2]), "+f"((d)[3]) \
        : "r"((a)[0]), "r"((a)[1]), "r"((a)[2]), "r"((a)[3]), \
          "r"((b)[0]), "r"((b)[1]))

// Tile geometry
#define TM   128           // CTA tile M
#define TN   128           // CTA tile N
#define TK   32            // K chunk
#define SPAD 36            // smem row stride in floats (conflict-free frag LDS)
#define TSZ  (128 * SPAD)  // one operand tile in floats

// ---------------------------------------------------------------------------
// tf32 mma.sync GEMM:  C = scale * (A @ B^T) + bias
// A: [M x K] row-major fp32, B: [N x K] row-major fp32 (K-major both).
// 256 threads = 8 warps in 2(m) x 4(n) grid; warp tile 64x32;
// per warp per k8: 4x4 m16n8k8 mmas. Double-buffered smem (72 KB dynamic).
// All dims multiples of tile sizes.
// ---------------------------------------------------------------------------
__global__ void __launch_bounds__(256)
gemm_mma(const float* __restrict__ A, const float* __restrict__ B,
         const float* __restrict__ bias, float* __restrict__ C,
         int lda, int ldb, int ldc,
         long sA, long sB, long sC,
         int K, float scale)
{
    extern __shared__ float sm[];
    float* const Asb[2] = { sm,            sm + 2 * TSZ };
    float* const Bsb[2] = { sm + TSZ,      sm + 3 * TSZ };

    const int tid = threadIdx.x;
    const int wid = tid >> 5;
    const int lid = tid & 31;
    const int g   = lid >> 2;       // fragment group row 0..7
    const int t   = lid & 3;        // fragment k sub-col 0..3

    const int bz = blockIdx.z;
    A += (long)bz * sA;  B += (long)bz * sB;  C += (long)bz * sC;
    const int bm = blockIdx.y * TM;
    const int bn = blockIdx.x * TN;

    const int wm = (wid >> 2) * 64; // warp m offset in tile
    const int wn = (wid & 3) * 32;  // warp n offset in tile

    // global-load assignment: 4 rows x 1 float4 per thread per operand
    const int ldr  = tid >> 3;        // 0..31 (base row)
    const int ldc4 = (tid & 7) * 4;   // float col 0,4,...,28

    float acc[4][4][4];
#pragma unroll
    for (int i = 0; i < 4; i++)
#pragma unroll
        for (int j = 0; j < 4; j++)
#pragma unroll
            for (int r = 0; r < 4; r++) acc[i][j][r] = 0.f;

    const int nc = K / TK;
    float4 ra[4], rb[4];

    // ---- prologue: load + store chunk 0 ----
#pragma unroll
    for (int u = 0; u < 4; u++) {
        const int row = ldr + u * 32;
        ra[u] = *(const float4*)(A + (long)(bm + row) * lda + ldc4);
        rb[u] = *(const float4*)(B + (long)(bn + row) * ldb + ldc4);
    }
#pragma unroll
    for (int u = 0; u < 4; u++) {
        const int row = ldr + u * 32;
        uint32_t* pa = (uint32_t*)&Asb[0][row * SPAD + ldc4];
        pa[0] = tf32cvt(ra[u].x); pa[1] = tf32cvt(ra[u].y);
        pa[2] = tf32cvt(ra[u].z); pa[3] = tf32cvt(ra[u].w);
        uint32_t* pb = (uint32_t*)&Bsb[0][row * SPAD + ldc4];
        pb[0] = tf32cvt(rb[u].x); pb[1] = tf32cvt(rb[u].y);
        pb[2] = tf32cvt(rb[u].z); pb[3] = tf32cvt(rb[u].w);
    }
    __syncthreads();

    for (int c = 0; c < nc; c++) {
        const int s = c & 1;
        // issue next chunk's global loads early
        if (c + 1 < nc) {
            const int k0 = (c + 1) * TK;
#pragma unroll
            for (int u = 0; u < 4; u++) {
                const int row = ldr + u * 32;
                ra[u] = *(const float4*)(A + (long)(bm + row) * lda + k0 + ldc4);
                rb[u] = *(const float4*)(B + (long)(bn + row) * ldb + k0 + ldc4);
            }
        }

        // compute on buffer s
        const uint32_t* __restrict__ Asu = (const uint32_t*)Asb[s];
        const uint32_t* __restrict__ Bsu = (const uint32_t*)Bsb[s];
#pragma unroll
        for (int ks = 0; ks < 4; ks++) {
            const int kk = ks * 8;
            uint32_t af[4][4], bf[4][2];
#pragma unroll
            for (int mi = 0; mi < 4; mi++) {
                const int base = (wm + mi * 16 + g) * SPAD + kk + t;
                af[mi][0] = Asu[base];
                af[mi][1] = Asu[base + 8 * SPAD];
                af[mi][2] = Asu[base + 4];
                af[mi][3] = Asu[base + 8 * SPAD + 4];
            }
#pragma unroll
            for (int ni = 0; ni < 4; ni++) {
                const int base = (wn + ni * 8 + g) * SPAD + kk + t;
                bf[ni][0] = Bsu[base];
                bf[ni][1] = Bsu[base + 4];
            }
#pragma unroll
            for (int mi = 0; mi < 4; mi++)
#pragma unroll
                for (int ni = 0; ni < 4; ni++)
                    MMA_TF32(acc[mi][ni], af[mi], bf[ni]);
        }

        // store next chunk into the other buffer
        if (c + 1 < nc) {
            const int d = (c + 1) & 1;
#pragma unroll
            for (int u = 0; u < 4; u++) {
                const int row = ldr + u * 32;
                uint32_t* pa = (uint32_t*)&Asb[d][row * SPAD + ldc4];
                pa[0] = tf32cvt(ra[u].x); pa[1] = tf32cvt(ra[u].y);
                pa[2] = tf32cvt(ra[u].z); pa[3] = tf32cvt(ra[u].w);
                uint32_t* pb = (uint32_t*)&Bsb[d][row * SPAD + ldc4];
                pb[0] = tf32cvt(rb[u].x); pb[1] = tf32cvt(rb[u].y);
                pb[2] = tf32cvt(rb[u].z); pb[3] = tf32cvt(rb[u].w);
            }
        }
        __syncthreads();
    }

    // ---- epilogue ----
#pragma unroll
    for (int mi = 0; mi < 4; mi++) {
        const int row0 = bm + wm + mi * 16 + g;
#pragma unroll
        for (int ni = 0; ni < 4; ni++) {
            const int col = bn + wn + ni * 8 + 2 * t;
            float bx = 0.f, by = 0.f;
            if (bias) { bx = bias[col]; by = bias[col + 1]; }
            float2 v0, v1;
            v0.x = acc[mi][ni][0] * scale + bx;
            v0.y = acc[mi][ni][1] * scale + by;
            v1.x = acc[mi][ni][2] * scale + bx;
            v1.y = acc[mi][ni][3] * scale + by;
            *(float2*)(C + (long)row0 * ldc + col)       = v0;
            *(float2*)(C + (long)(row0 + 8) * ldc + col) = v1;
        }
    }
}

#define GEMM_SMEM (4 * TSZ * 4)   // 73728 bytes

// ---------------------------------------------------------------------------
// V transpose: Vt[b][d][s] = V[b][s][d]
// ---------------------------------------------------------------------------
__global__ __launch_bounds__(256) void transpose_kernel(
    const float* __restrict__ V, float* __restrict__ Vt)
{
    __shared__ float t[32][33];
    const int b  = blockIdx.z;
    const int s0 = blockIdx.x * 32;
    const int d0 = blockIdx.y * 32;
#pragma unroll
    for (int i = threadIdx.y; i < 32; i += 8)
        t[i][threadIdx.x] = V[((long)b * SEQ + s0 + i) * DIM + d0 + threadIdx.x];
    __syncthreads();
#pragma unroll
    for (int i = threadIdx.y; i < 32; i += 8)
        Vt[((long)b * DIM + d0 + i) * SEQ + s0 + threadIdx.x] = t[threadIdx.x][i];
}

// ---------------------------------------------------------------------------
// Row-wise masked softmax over the key axis (2048 = 256 thr * 8 vals).
// ---------------------------------------------------------------------------
__global__ __launch_bounds__(256) void softmax_kernel(
    float* __restrict__ S, const int* __restrict__ mask)
{
    const int row = blockIdx.x;
    const int b   = row / SEQ;
    float* s = S + (size_t)row * SEQ;
    const int* m = mask + b * SEQ;

    float v[8];
    float mx = -3.0e38f;
#pragma unroll
    for (int t = 0; t < 8; t++) {
        const int k = threadIdx.x + t * 256;
        float x = s[k];
        if (m[k] == 0) x = -1e9f;
        v[t] = x;
        mx = fmaxf(mx, x);
    }
    __shared__ float red[256];
    red[threadIdx.x] = mx;
    __syncthreads();
    for (int o = 128; o > 0; o >>= 1) {
        if (threadIdx.x < o) red[threadIdx.x] = fmaxf(red[threadIdx.x], red[threadIdx.x + o]);
        __syncthreads();
    }
    mx = red[0];
    __syncthreads();

    float sum = 0.f;
#pragma unroll
    for (int t = 0; t < 8; t++) { v[t] = __expf(v[t] - mx); sum += v[t]; }
    red[threadIdx.x] = sum;
    __syncthreads();
    for (int o = 128; o > 0; o >>= 1) {
        if (threadIdx.x < o) red[threadIdx.x] += red[threadIdx.x + o];
        __syncthreads();
    }
    const float inv = 1.f / red[0];
#pragma unroll
    for (int t = 0; t < 8; t++)
        s[threadIdx.x + t * 256] = v[t] * inv;
}

// ---------------------------------------------------------------------------
extern "C" void kernel_launch(void* const* d_in, const int* in_sizes, int n_in,
                              void* d_out, int out_size)
{
    const float* x    = (const float*)d_in[0];
    const int*   mask = (const int*)  d_in[1];
    const float* Wk   = (const float*)d_in[2];
    const float* bk   = (const float*)d_in[3];
    const float* Wq   = (const float*)d_in[4];
    const float* bq   = (const float*)d_in[5];
    const float* Wv   = (const float*)d_in[6];
    const float* bv   = (const float*)d_in[7];
    float* out = (float*)d_out;

    float *Q, *Kp, *V, *Vt, *S;
    cudaGetSymbolAddress((void**)&Q,  g_Q);
    cudaGetSymbolAddress((void**)&Kp, g_K);
    cudaGetSymbolAddress((void**)&V,  g_V);
    cudaGetSymbolAddress((void**)&Vt, g_Vt);
    cudaGetSymbolAddress((void**)&S,  g_S);

    cudaFuncSetAttribute(gemm_mma, cudaFuncAttributeMaxDynamicSharedMemorySize, GEMM_SMEM);

    // QKV projections: [16384 x 512] = x @ W^T + b  (W is [out,in] = K-major)
    dim3 gp(DIM / TN, (BB * SEQ) / TM, 1);
    gemm_mma<<<gp, 256, GEMM_SMEM>>>(x, Wq, bq, Q,  DIM, DIM, DIM, 0, 0, 0, DIM, 1.f);
    gemm_mma<<<gp, 256, GEMM_SMEM>>>(x, Wk, bk, Kp, DIM, DIM, DIM, 0, 0, 0, DIM, 1.f);
    gemm_mma<<<gp, 256, GEMM_SMEM>>>(x, Wv, bv, V,  DIM, DIM, DIM, 0, 0, 0, DIM, 1.f);

    // V transpose for the AV GEMM (B operand must be [N x K] K-major)
    transpose_kernel<<<dim3(SEQ / 32, DIM / 32, BB), dim3(32, 8)>>>(V, Vt);

    // scores: S[b] = Q[b] @ K[b]^T / sqrt(D)
    const float inv_sqrt_d = 0.044194173824159216f;
    dim3 gs(SEQ / TN, SEQ / TM, BB);
    gemm_mma<<<gs, 256, GEMM_SMEM>>>(Q, Kp, nullptr, S,
                                     DIM, DIM, SEQ,
                                     (long)SEQ * DIM, (long)SEQ * DIM, (long)SEQ * SEQ,
                                     DIM, inv_sqrt_d);

    // masked softmax
    softmax_kernel<<<BB * SEQ, 256>>>(S, mask);

    // out[b] = P[b] @ Vt[b]^T   (Vt is [D x SEQ], K-major over SEQ)
    dim3 ga(DIM / TN, SEQ / TM, BB);
    gemm_mma<<<ga, 256, GEMM_SMEM>>>(S, Vt, nullptr, out,
                                     SEQ, SEQ, DIM,
                                     (long)SEQ * SEQ, (long)SEQ * DIM, (long)SEQ * DIM,
                                     SEQ, 1.f);
}

// round 7
// speedup vs baseline: 3.8625x; 2.1851x over previous
#include <cuda_runtime.h>
#include <cstdint>

#define BB   8
#define SEQ  2048
#define DIM  512

// Scratch (device globals; no allocs allowed)
__device__ float g_Q [(size_t)BB * SEQ * DIM];
__device__ float g_K [(size_t)BB * SEQ * DIM];
__device__ float g_V [(size_t)BB * SEQ * DIM];
__device__ float g_Vt[(size_t)BB * SEQ * DIM];
__device__ float g_S [(size_t)BB * SEQ * SEQ];
__device__ float g_Xr[(size_t)BB * SEQ * DIM];   // tf32-rounded x
__device__ float g_Wr[3 * (size_t)DIM * DIM];    // tf32-rounded Wq|Wk|Wv

__device__ __forceinline__ uint32_t tf32cvt(float f) {
    uint32_t r; asm("cvt.rna.tf32.f32 %0, %1;" : "=r"(r) : "f"(f)); return r;
}
__device__ __forceinline__ float tf32round(float f) {
    return __uint_as_float(tf32cvt(f));
}
__device__ __forceinline__ uint32_t smem_u32(const void* p) {
    uint32_t a;
    asm("{ .reg .u64 t; cvta.to.shared.u64 t, %1; cvt.u32.u64 %0, t; }" : "=r"(a) : "l"(p));
    return a;
}
__device__ __forceinline__ void ldsm4(uint32_t* r, uint32_t addr) {
    asm volatile("ldmatrix.sync.aligned.m8n8.x4.shared.b16 {%0,%1,%2,%3}, [%4];"
                 : "=r"(r[0]), "=r"(r[1]), "=r"(r[2]), "=r"(r[3]) : "r"(addr));
}
#define CP_ASYNC16(s, g) \
    asm volatile("cp.async.cg.shared.global [%0], [%1], 16;" :: "r"(s), "l"(g))
#define CP_COMMIT() asm volatile("cp.async.commit_group;" ::: "memory")
#define CP_WAIT1()  asm volatile("cp.async.wait_group 1;"  ::: "memory")

#define MMA_TF32(d, a, b) \
    asm volatile( \
        "mma.sync.aligned.m16n8k8.row.col.f32.tf32.tf32.f32 " \
        "{%0,%1,%2,%3}, {%4,%5,%6,%7}, {%8,%9}, {%0,%1,%2,%3};" \
        : "+f"((d)[0]), "+f"((d)[1]), "+f"((d)[2]), "+f"((d)[3]) \
        : "r"((a)[0]), "r"((a)[1]), "r"((a)[2]), "r"((a)[3]), \
          "r"((b)[0]), "r"((b)[1]))

#define SW(o) ((o) ^ (((o) >> 3) & 0x70))

#define TM 128
#define TN 128
#define TK 32
#define NSTAGE 3
#define STAGE_BYTES 32768
#define GEMM_SMEM (NSTAGE * STAGE_BYTES + 1024)

// ---------------------------------------------------------------------------
// tf32 mma.sync GEMM:  C = scale * (A @ B^T) + bias  [+ optional tf32 round]
// A: [M x K] row-major, B: [N x K] row-major; BOTH ALREADY tf32-ROUNDED.
// 256 threads = 8 warps (2m x 4n), warp tile 64x32, ldmatrix fragments,
// 3-stage cp.async pipeline.
// ---------------------------------------------------------------------------
__global__ void __launch_bounds__(256)
gemm_mma(const float* __restrict__ A, const float* __restrict__ B,
         const float* __restrict__ bias, float* __restrict__ C,
         int lda, int ldb, int ldc,
         long sA, long sB, long sC,
         int K, float scale, int round_out)
{
    extern __shared__ char smraw[];
    const uint32_t sbase = (smem_u32(smraw) + 1023u) & ~1023u;

    const int tid = threadIdx.x;
    const int wid = tid >> 5;
    const int lid = tid & 31;
    const int g   = lid >> 2;
    const int t   = lid & 3;

    const int bz = blockIdx.z;
    A += (long)bz * sA;  B += (long)bz * sB;  C += (long)bz * sC;
    const int bm = blockIdx.y * TM;
    const int bn = blockIdx.x * TN;

    const int wm = (wid >> 2) * 64;
    const int wn = (wid & 3) * 32;

    const int aRowL = lid & 15;
    const int akh   = lid >> 4;
    const int bRowL = (lid & 7) + ((lid >> 4) & 1) * 8;
    const int bkh   = (lid >> 3) & 1;

    const int ldr  = tid >> 3;
    const int lc16 = tid & 7;

    float acc[4][4][4];
#pragma unroll
    for (int i = 0; i < 4; i++)
#pragma unroll
        for (int j = 0; j < 4; j++)
#pragma unroll
            for (int r = 0; r < 4; r++) acc[i][j][r] = 0.f;

    const int nc = K / TK;

    auto issue = [&](int c) {
        const int st = c % NSTAGE;
        const uint32_t As = sbase + st * STAGE_BYTES;
        const uint32_t Bs = As + 16384;
        const int k0 = c * TK;
#pragma unroll
        for (int u = 0; u < 4; u++) {
            const int row = ldr + u * 32;
            const uint32_t so = SW((row << 7) + (lc16 << 4));
            CP_ASYNC16(As + so, A + (long)(bm + row) * lda + k0 + lc16 * 4);
            CP_ASYNC16(Bs + so, B + (long)(bn + row) * ldb + k0 + lc16 * 4);
        }
    };

    issue(0); CP_COMMIT();
    issue(1); CP_COMMIT();

    for (int c = 0; c < nc; c++) {
        CP_WAIT1();
        __syncthreads();

        const int st = c % NSTAGE;
        const uint32_t As = sbase + st * STAGE_BYTES;
        const uint32_t Bs = As + 16384;

#pragma unroll
        for (int ks = 0; ks < 4; ks++) {
            uint32_t af[4][4], bf[2][4];
#pragma unroll
            for (int mi = 0; mi < 4; mi++) {
                const int off = ((wm + mi * 16 + aRowL) << 7) + ((ks * 2 + akh) << 4);
                ldsm4(af[mi], As + SW(off));
            }
#pragma unroll
            for (int nb = 0; nb < 2; nb++) {
                const int off = ((wn + nb * 16 + bRowL) << 7) + ((ks * 2 + bkh) << 4);
                ldsm4(bf[nb], Bs + SW(off));
            }
#pragma unroll
            for (int mi = 0; mi < 4; mi++)
#pragma unroll
                for (int ni = 0; ni < 4; ni++)
                    MMA_TF32(acc[mi][ni], af[mi], &bf[ni >> 1][(ni & 1) * 2]);
        }

        __syncthreads();
        if (c + 2 < nc) issue(c + 2);
        CP_COMMIT();
    }

#pragma unroll
    for (int mi = 0; mi < 4; mi++) {
        const int row0 = bm + wm + mi * 16 + g;
#pragma unroll
        for (int ni = 0; ni < 4; ni++) {
            const int col = bn + wn + ni * 8 + 2 * t;
            float bx = 0.f, by = 0.f;
            if (bias) { bx = bias[col]; by = bias[col + 1]; }
            float2 v0, v1;
            v0.x = acc[mi][ni][0] * scale + bx;
            v0.y = acc[mi][ni][1] * scale + by;
            v1.x = acc[mi][ni][2] * scale + bx;
            v1.y = acc[mi][ni][3] * scale + by;
            if (round_out) {
                v0.x = tf32round(v0.x); v0.y = tf32round(v0.y);
                v1.x = tf32round(v1.x); v1.y = tf32round(v1.y);
            }
            *(float2*)(C + (long)row0 * ldc + col)       = v0;
            *(float2*)(C + (long)(row0 + 8) * ldc + col) = v1;
        }
    }
}

__global__ __launch_bounds__(256) void round_kernel(
    const float4* __restrict__ in, float4* __restrict__ out, int n4)
{
    const int i = blockIdx.x * blockDim.x + threadIdx.x;
    if (i < n4) {
        float4 v = in[i];
        v.x = tf32round(v.x); v.y = tf32round(v.y);
        v.z = tf32round(v.z); v.w = tf32round(v.w);
        out[i] = v;
    }
}

__global__ __launch_bounds__(256) void transpose_kernel(
    const float* __restrict__ V, float* __restrict__ Vt)
{
    __shared__ float t[32][33];
    const int b  = blockIdx.z;
    const int s0 = blockIdx.x * 32;
    const int d0 = blockIdx.y * 32;
#pragma unroll
    for (int i = threadIdx.y; i < 32; i += 8)
        t[i][threadIdx.x] = V[((long)b * SEQ + s0 + i) * DIM + d0 + threadIdx.x];
    __syncthreads();
#pragma unroll
    for (int i = threadIdx.y; i < 32; i += 8)
        Vt[((long)b * DIM + d0 + i) * SEQ + s0 + threadIdx.x] = t[threadIdx.x][i];
}

__global__ __launch_bounds__(256) void softmax_kernel(
    float* __restrict__ S, const int* __restrict__ mask)
{
    const int row = blockIdx.x;
    const int b   = row / SEQ;
    float* s = S + (size_t)row * SEQ;
    const int* m = mask + b * SEQ;

    float v[8];
    float mx = -3.0e38f;
#pragma unroll
    for (int t = 0; t < 8; t++) {
        const int k = threadIdx.x + t * 256;
        float x = s[k];
        if (m[k] == 0) x = -1e9f;
        v[t] = x;
        mx = fmaxf(mx, x);
    }
    __shared__ float red[256];
    red[threadIdx.x] = mx;
    __syncthreads();
    for (int o = 128; o > 0; o >>= 1) {
        if (threadIdx.x < o) red[threadIdx.x] = fmaxf(red[threadIdx.x], red[threadIdx.x + o]);
        __syncthreads();
    }
    mx = red[0];
    __syncthreads();

    float sum = 0.f;
#pragma unroll
    for (int t = 0; t < 8; t++) { v[t] = __expf(v[t] - mx); sum += v[t]; }
    red[threadIdx.x] = sum;
    __syncthreads();
    for (int o = 128; o > 0; o >>= 1) {
        if (threadIdx.x < o) red[threadIdx.x] += red[threadIdx.x + o];
        __syncthreads();
    }
    const float inv = 1.f / red[0];
#pragma unroll
    for (int t = 0; t < 8; t++)
        s[threadIdx.x + t * 256] = tf32round(v[t] * inv);
}

extern "C" void kernel_launch(void* const* d_in, const int* in_sizes, int n_in,
                              void* d_out, int out_size)
{
    const float* x    = (const float*)d_in[0];
    const int*   mask = (const int*)  d_in[1];
    const float* Wk   = (const float*)d_in[2];
    const float* bk   = (const float*)d_in[3];
    const float* Wq   = (const float*)d_in[4];
    const float* bq   = (const float*)d_in[5];
    const float* Wv   = (const float*)d_in[6];
    const float* bv   = (const float*)d_in[7];
    float* out = (float*)d_out;

    float *Q, *Kp, *V, *Vt, *S, *Xr, *Wr;
    cudaGetSymbolAddress((void**)&Q,  g_Q);
    cudaGetSymbolAddress((void**)&Kp, g_K);
    cudaGetSymbolAddress((void**)&V,  g_V);
    cudaGetSymbolAddress((void**)&Vt, g_Vt);
    cudaGetSymbolAddress((void**)&S,  g_S);
    cudaGetSymbolAddress((void**)&Xr, g_Xr);
    cudaGetSymbolAddress((void**)&Wr, g_Wr);

    cudaFuncSetAttribute(gemm_mma, cudaFuncAttributeMaxDynamicSharedMemorySize, GEMM_SMEM);

    // prepass: slot0=Wq, slot1=Wk, slot2=Wv
    const int xN4 = BB * SEQ * DIM / 4;
    const int wN4 = DIM * DIM / 4;
    round_kernel<<<(xN4 + 255) / 256, 256>>>((const float4*)x, (float4*)Xr, xN4);
    round_kernel<<<(wN4 + 255) / 256, 256>>>((const float4*)Wq, (float4*)(Wr + 0L * DIM * DIM), wN4);
    round_kernel<<<(wN4 + 255) / 256, 256>>>((const float4*)Wk, (float4*)(Wr + 1L * DIM * DIM), wN4);
    round_kernel<<<(wN4 + 255) / 256, 256>>>((const float4*)Wv, (float4*)(Wr + 2L * DIM * DIM), wN4);

    dim3 gp(DIM / TN, (BB * SEQ) / TM, 1);
    gemm_mma<<<gp, 256, GEMM_SMEM>>>(Xr, Wr + 0L * DIM * DIM, bq, Q,
                                     DIM, DIM, DIM, 0, 0, 0, DIM, 1.f, 1);
    gemm_mma<<<gp, 256, GEMM_SMEM>>>(Xr, Wr + 1L * DIM * DIM, bk, Kp,
                                     DIM, DIM, DIM, 0, 0, 0, DIM, 1.f, 1);
    gemm_mma<<<gp, 256, GEMM_SMEM>>>(Xr, Wr + 2L * DIM * DIM, bv, V,
                                     DIM, DIM, DIM, 0, 0, 0, DIM, 1.f, 1);

    transpose_kernel<<<dim3(SEQ / 32, DIM / 32, BB), dim3(32, 8)>>>(V, Vt);

    const float inv_sqrt_d = 0.044194173824159216f;
    dim3 gs(SEQ / TN, SEQ / TM, BB);
    gemm_mma<<<gs, 256, GEMM_SMEM>>>(Q, Kp, nullptr, S,
                                     DIM, DIM, SEQ,
                                     (long)SEQ * DIM, (long)SEQ * DIM, (long)SEQ * SEQ,
                                     DIM, inv_sqrt_d, 0);

    softmax_kernel<<<BB * SEQ, 256>>>(S, mask);

    dim3 ga(DIM / TN, SEQ / TM, BB);
    gemm_mma<<<ga, 256, GEMM_SMEM>>>(S, Vt, nullptr, out,
                                     SEQ, SEQ, DIM,
                                     (long)SEQ * SEQ, (long)SEQ * DIM, (long)SEQ * DIM,
                                     SEQ, 1.f, 0);
}

// round 8
// speedup vs baseline: 3.9300x; 1.0175x over previous
#include <cuda_runtime.h>
#include <cstdint>

#define BB   8
#define SEQ  2048
#define DIM  512

// Scratch (device globals; no allocs allowed)
__device__ float g_QKV[3 * (size_t)BB * SEQ * DIM];  // Q | K | V (contiguous)
__device__ float g_Vt [(size_t)BB * SEQ * DIM];
__device__ float g_S  [(size_t)BB * SEQ * SEQ];
__device__ float g_Xr [(size_t)BB * SEQ * DIM];      // tf32-rounded x
__device__ float g_Wr [3 * (size_t)DIM * DIM];       // tf32-rounded Wq|Wk|Wv
__device__ float g_b  [3 * DIM];                     // packed bq|bk|bv

__device__ __forceinline__ uint32_t tf32cvt(float f) {
    uint32_t r; asm("cvt.rna.tf32.f32 %0, %1;" : "=r"(r) : "f"(f)); return r;
}
__device__ __forceinline__ float tf32round(float f) {
    return __uint_as_float(tf32cvt(f));
}
__device__ __forceinline__ uint32_t smem_u32(const void* p) {
    uint32_t a;
    asm("{ .reg .u64 t; cvta.to.shared.u64 t, %1; cvt.u32.u64 %0, t; }" : "=r"(a) : "l"(p));
    return a;
}
__device__ __forceinline__ void ldsm4(uint32_t* r, uint32_t addr) {
    asm volatile("ldmatrix.sync.aligned.m8n8.x4.shared.b16 {%0,%1,%2,%3}, [%4];"
                 : "=r"(r[0]), "=r"(r[1]), "=r"(r[2]), "=r"(r[3]) : "r"(addr));
}
#define CP_ASYNC16(s, g) \
    asm volatile("cp.async.cg.shared.global [%0], [%1], 16;" :: "r"(s), "l"(g))
#define CP_COMMIT() asm volatile("cp.async.commit_group;" ::: "memory")
#define CP_WAIT1()  asm volatile("cp.async.wait_group 1;"  ::: "memory")

#define MMA_TF32(d, a, b) \
    asm volatile( \
        "mma.sync.aligned.m16n8k8.row.col.f32.tf32.tf32.f32 " \
        "{%0,%1,%2,%3}, {%4,%5,%6,%7}, {%8,%9}, {%0,%1,%2,%3};" \
        : "+f"((d)[0]), "+f"((d)[1]), "+f"((d)[2]), "+f"((d)[3]) \
        : "r"((a)[0]), "r"((a)[1]), "r"((a)[2]), "r"((a)[3]), \
          "r"((b)[0]), "r"((b)[1]))

#define SW(o) ((o) ^ (((o) >> 3) & 0x70))

#define TM 128
#define TN 128
#define TK 32
#define NSTAGE 3
#define STAGE_BYTES 32768
#define GEMM_SMEM (NSTAGE * STAGE_BYTES + 1024)

// ---------------------------------------------------------------------------
// tf32 mma.sync GEMM:  C = scale * (A @ B^T) + bias  [+ optional tf32 round]
// A: [M x K] row-major, B: [N x K] row-major; BOTH ALREADY tf32-ROUNDED.
// 256 threads = 8 warps (2m x 4n), warp tile 64x32, ldmatrix fragments,
// 3-stage cp.async pipeline, one barrier per K-chunk.
// grid.z batches via strides (sA/sB/sC/sBias may be 0).
// ---------------------------------------------------------------------------
__global__ void __launch_bounds__(256, 2)
gemm_mma(const float* __restrict__ A, const float* __restrict__ B,
         const float* __restrict__ bias, float* __restrict__ C,
         int lda, int ldb, int ldc,
         long sA, long sB, long sC, long sBias,
         int K, float scale, int round_out)
{
    extern __shared__ char smraw[];
    const uint32_t sbase = (smem_u32(smraw) + 1023u) & ~1023u;

    const int tid = threadIdx.x;
    const int wid = tid >> 5;
    const int lid = tid & 31;
    const int g   = lid >> 2;
    const int t   = lid & 3;

    const int bz = blockIdx.z;
    A += (long)bz * sA;  B += (long)bz * sB;  C += (long)bz * sC;
    if (bias) bias += (long)bz * sBias;
    const int bm = blockIdx.y * TM;
    const int bn = blockIdx.x * TN;

    const int wm = (wid >> 2) * 64;
    const int wn = (wid & 3) * 32;

    const int aRowL = lid & 15;
    const int akh   = lid >> 4;
    const int bRowL = (lid & 7) + ((lid >> 4) & 1) * 8;
    const int bkh   = (lid >> 3) & 1;

    const int ldr  = tid >> 3;
    const int lc16 = tid & 7;

    float acc[4][4][4];
#pragma unroll
    for (int i = 0; i < 4; i++)
#pragma unroll
        for (int j = 0; j < 4; j++)
#pragma unroll
            for (int r = 0; r < 4; r++) acc[i][j][r] = 0.f;

    const int nc = K / TK;

    auto issue = [&](int c) {
        const int st = c % NSTAGE;
        const uint32_t As = sbase + st * STAGE_BYTES;
        const uint32_t Bs = As + 16384;
        const int k0 = c * TK;
#pragma unroll
        for (int u = 0; u < 4; u++) {
            const int row = ldr + u * 32;
            const uint32_t so = SW((row << 7) + (lc16 << 4));
            CP_ASYNC16(As + so, A + (long)(bm + row) * lda + k0 + lc16 * 4);
            CP_ASYNC16(Bs + so, B + (long)(bn + row) * ldb + k0 + lc16 * 4);
        }
    };

    issue(0); CP_COMMIT();
    issue(1); CP_COMMIT();

    for (int c = 0; c < nc; c++) {
        CP_WAIT1();
        __syncthreads();   // all warps done reading stage c-1, data of stage c visible

        const int st = c % NSTAGE;
        const uint32_t As = sbase + st * STAGE_BYTES;
        const uint32_t Bs = As + 16384;

        // prefetch next chunk into the stage we just vacated (c-1 mod 3)
        if (c + 2 < nc) issue(c + 2);
        CP_COMMIT();

#pragma unroll
        for (int ks = 0; ks < 4; ks++) {
            uint32_t af[4][4], bf[2][4];
#pragma unroll
            for (int mi = 0; mi < 4; mi++) {
                const int off = ((wm + mi * 16 + aRowL) << 7) + ((ks * 2 + akh) << 4);
                ldsm4(af[mi], As + SW(off));
            }
#pragma unroll
            for (int nb = 0; nb < 2; nb++) {
                const int off = ((wn + nb * 16 + bRowL) << 7) + ((ks * 2 + bkh) << 4);
                ldsm4(bf[nb], Bs + SW(off));
            }
#pragma unroll
            for (int mi = 0; mi < 4; mi++)
#pragma unroll
                for (int ni = 0; ni < 4; ni++)
                    MMA_TF32(acc[mi][ni], af[mi], &bf[ni >> 1][(ni & 1) * 2]);
        }
    }

#pragma unroll
    for (int mi = 0; mi < 4; mi++) {
        const int row0 = bm + wm + mi * 16 + g;
#pragma unroll
        for (int ni = 0; ni < 4; ni++) {
            const int col = bn + wn + ni * 8 + 2 * t;
            float bx = 0.f, by = 0.f;
            if (bias) { bx = bias[col]; by = bias[col + 1]; }
            float2 v0, v1;
            v0.x = acc[mi][ni][0] * scale + bx;
            v0.y = acc[mi][ni][1] * scale + by;
            v1.x = acc[mi][ni][2] * scale + bx;
            v1.y = acc[mi][ni][3] * scale + by;
            if (round_out) {
                v0.x = tf32round(v0.x); v0.y = tf32round(v0.y);
                v1.x = tf32round(v1.x); v1.y = tf32round(v1.y);
            }
            *(float2*)(C + (long)row0 * ldc + col)       = v0;
            *(float2*)(C + (long)(row0 + 8) * ldc + col) = v1;
        }
    }
}

// ---------------------------------------------------------------------------
__global__ __launch_bounds__(256) void round_kernel(
    const float4* __restrict__ in, float4* __restrict__ out, int n4)
{
    const int i = blockIdx.x * blockDim.x + threadIdx.x;
    if (i < n4) {
        float4 v = in[i];
        v.x = tf32round(v.x); v.y = tf32round(v.y);
        v.z = tf32round(v.z); v.w = tf32round(v.w);
        out[i] = v;
    }
}

// Pack bq|bk|bv into one buffer (order: Q, K, V to match g_QKV slots)
__global__ void pack_bias_kernel(const float* __restrict__ bq,
                                 const float* __restrict__ bk,
                                 const float* __restrict__ bv,
                                 float* __restrict__ dst)
{
    const int i = threadIdx.x + blockIdx.x * blockDim.x;
    if (i < DIM) {
        dst[i]           = bq[i];
        dst[DIM + i]     = bk[i];
        dst[2 * DIM + i] = bv[i];
    }
}

// ---------------------------------------------------------------------------
__global__ __launch_bounds__(256) void transpose_kernel(
    const float* __restrict__ V, float* __restrict__ Vt)
{
    __shared__ float t[32][33];
    const int b  = blockIdx.z;
    const int s0 = blockIdx.x * 32;
    const int d0 = blockIdx.y * 32;
#pragma unroll
    for (int i = threadIdx.y; i < 32; i += 8)
        t[i][threadIdx.x] = V[((long)b * SEQ + s0 + i) * DIM + d0 + threadIdx.x];
    __syncthreads();
#pragma unroll
    for (int i = threadIdx.y; i < 32; i += 8)
        Vt[((long)b * DIM + d0 + i) * SEQ + s0 + threadIdx.x] = t[threadIdx.x][i];
}

// ---------------------------------------------------------------------------
// Row-wise masked softmax (key axis). 2048 = 256 thr * 2 float4.
// Warp-shuffle reductions; output rounded to tf32 for the AV GEMM cp.async.
// ---------------------------------------------------------------------------
__global__ __launch_bounds__(256) void softmax_kernel(
    float* __restrict__ S, const int* __restrict__ mask)
{
    const int row = blockIdx.x;
    const int b   = row / SEQ;
    float4* s = (float4*)(S + (size_t)row * SEQ);
    const int4* m = (const int4*)(mask + b * SEQ);

    const int i0 = threadIdx.x;
    const int i1 = threadIdx.x + 256;

    float4 v0 = s[i0], v1 = s[i1];
    const int4 m0 = m[i0], m1 = m[i1];
    if (m0.x == 0) v0.x = -1e9f;
    if (m0.y == 0) v0.y = -1e9f;
    if (m0.z == 0) v0.z = -1e9f;
    if (m0.w == 0) v0.w = -1e9f;
    if (m1.x == 0) v1.x = -1e9f;
    if (m1.y == 0) v1.y = -1e9f;
    if (m1.z == 0) v1.z = -1e9f;
    if (m1.w == 0) v1.w = -1e9f;

    float mx = fmaxf(fmaxf(fmaxf(v0.x, v0.y), fmaxf(v0.z, v0.w)),
                     fmaxf(fmaxf(v1.x, v1.y), fmaxf(v1.z, v1.w)));
    __shared__ float red[8];
#pragma unroll
    for (int o = 16; o > 0; o >>= 1)
        mx = fmaxf(mx, __shfl_xor_sync(0xFFFFFFFF, mx, o));
    if ((threadIdx.x & 31) == 0) red[threadIdx.x >> 5] = mx;
    __syncthreads();
    {
        float r = red[threadIdx.x & 7];
#pragma unroll
        for (int o = 4; o > 0; o >>= 1)
            r = fmaxf(r, __shfl_xor_sync(0xFFFFFFFF, r, o));
        mx = r;
    }

    v0.x = __expf(v0.x - mx); v0.y = __expf(v0.y - mx);
    v0.z = __expf(v0.z - mx); v0.w = __expf(v0.w - mx);
    v1.x = __expf(v1.x - mx); v1.y = __expf(v1.y - mx);
    v1.z = __expf(v1.z - mx); v1.w = __expf(v1.w - mx);

    float sum = v0.x + v0.y + v0.z + v0.w + v1.x + v1.y + v1.z + v1.w;
#pragma unroll
    for (int o = 16; o > 0; o >>= 1)
        sum += __shfl_xor_sync(0xFFFFFFFF, sum, o);
    __syncthreads();
    if ((threadIdx.x & 31) == 0) red[threadIdx.x >> 5] = sum;
    __syncthreads();
    {
        float r = red[threadIdx.x & 7];
#pragma unroll
        for (int o = 4; o > 0; o >>= 1)
            r += __shfl_xor_sync(0xFFFFFFFF, r, o);
        sum = r;
    }

    const float inv = 1.f / sum;
    v0.x = tf32round(v0.x * inv); v0.y = tf32round(v0.y * inv);
    v0.z = tf32round(v0.z * inv); v0.w = tf32round(v0.w * inv);
    v1.x = tf32round(v1.x * inv); v1.y = tf32round(v1.y * inv);
    v1.z = tf32round(v1.z * inv); v1.w = tf32round(v1.w * inv);
    s[i0] = v0; s[i1] = v1;
}

// ---------------------------------------------------------------------------
extern "C" void kernel_launch(void* const* d_in, const int* in_sizes, int n_in,
                              void* d_out, int out_size)
{
    const float* x    = (const float*)d_in[0];
    const int*   mask = (const int*)  d_in[1];
    const float* Wk   = (const float*)d_in[2];
    const float* bk   = (const float*)d_in[3];
    const float* Wq   = (const float*)d_in[4];
    const float* bq   = (const float*)d_in[5];
    const float* Wv   = (const float*)d_in[6];
    const float* bv   = (const float*)d_in[7];
    float* out = (float*)d_out;

    float *QKV, *Vt, *S, *Xr, *Wr, *bias;
    cudaGetSymbolAddress((void**)&QKV,  g_QKV);
    cudaGetSymbolAddress((void**)&Vt,   g_Vt);
    cudaGetSymbolAddress((void**)&S,    g_S);
    cudaGetSymbolAddress((void**)&Xr,   g_Xr);
    cudaGetSymbolAddress((void**)&Wr,   g_Wr);
    cudaGetSymbolAddress((void**)&bias, g_b);

    const size_t PLANE = (size_t)BB * SEQ * DIM;   // one of Q/K/V
    float* Q  = QKV;
    float* Kp = QKV + PLANE;
    float* V  = QKV + 2 * PLANE;

    cudaFuncSetAttribute(gemm_mma, cudaFuncAttributeMaxDynamicSharedMemorySize, GEMM_SMEM);

    // prepass: round x and weights; pack biases. Wr slots: 0=Wq, 1=Wk, 2=Wv.
    const int xN4 = BB * SEQ * DIM / 4;
    const int wN4 = DIM * DIM / 4;
    round_kernel<<<(xN4 + 255) / 256, 256>>>((const float4*)x, (float4*)Xr, xN4);
    round_kernel<<<(wN4 + 255) / 256, 256>>>((const float4*)Wq, (float4*)(Wr + 0L * DIM * DIM), wN4);
    round_kernel<<<(wN4 + 255) / 256, 256>>>((const float4*)Wk, (float4*)(Wr + 1L * DIM * DIM), wN4);
    round_kernel<<<(wN4 + 255) / 256, 256>>>((const float4*)Wv, (float4*)(Wr + 2L * DIM * DIM), wN4);
    pack_bias_kernel<<<2, 256>>>(bq, bk, bv, bias);

    // merged QKV projection: grid.z selects (W, bias, output plane)
    dim3 gp(DIM / TN, (BB * SEQ) / TM, 3);
    gemm_mma<<<gp, 256, GEMM_SMEM>>>(Xr, Wr, bias, QKV,
                                     DIM, DIM, DIM,
                                     0, (long)DIM * DIM, (long)PLANE, DIM,
                                     DIM, 1.f, 1);

    transpose_kernel<<<dim3(SEQ / 32, DIM / 32, BB), dim3(32, 8)>>>(V, Vt);

    // scores: S[b] = Q[b] @ K[b]^T / sqrt(D)
    const float inv_sqrt_d = 0.044194173824159216f;
    dim3 gs(SEQ / TN, SEQ / TM, BB);
    gemm_mma<<<gs, 256, GEMM_SMEM>>>(Q, Kp, nullptr, S,
                                     DIM, DIM, SEQ,
                                     (long)SEQ * DIM, (long)SEQ * DIM, (long)SEQ * SEQ, 0,
                                     DIM, inv_sqrt_d, 0);

    softmax_kernel<<<BB * SEQ, 256>>>(S, mask);

    // out[b] = P[b] @ Vt[b]^T
    dim3 ga(DIM / TN, SEQ / TM, BB);
    gemm_mma<<<ga, 256, GEMM_SMEM>>>(S, Vt, nullptr, out,
                                     SEQ, SEQ, DIM,
                                     (long)SEQ * SEQ, (long)SEQ * DIM, (long)SEQ * DIM, 0,
                                     SEQ, 1.f, 0);
}

// round 10
// speedup vs baseline: 4.0984x; 1.0429x over previous
#include <cuda_runtime.h>
#include <cstdint>

#define BB   8
#define SEQ  2048
#define DIM  512

// Scratch (device globals; no allocs allowed)
__device__ float g_QKV[3 * (size_t)BB * SEQ * DIM];  // Q | K | V
__device__ float g_Vt [(size_t)BB * SEQ * DIM];
__device__ float g_S  [(size_t)BB * SEQ * SEQ];
__device__ float g_Xr [(size_t)BB * SEQ * DIM];      // tf32-rounded x
__device__ float g_Wr [3 * (size_t)DIM * DIM];       // tf32-rounded Wq|Wk|Wv
__device__ float g_b  [3 * DIM];                     // packed bq|bk|bv

__device__ __forceinline__ uint32_t tf32cvt(float f) {
    uint32_t r; asm("cvt.rna.tf32.f32 %0, %1;" : "=r"(r) : "f"(f)); return r;
}
__device__ __forceinline__ float tf32round(float f) {
    return __uint_as_float(tf32cvt(f));
}
__device__ __forceinline__ uint32_t smem_u32(const void* p) {
    uint32_t a;
    asm("{ .reg .u64 t; cvta.to.shared.u64 t, %1; cvt.u32.u64 %0, t; }" : "=r"(a) : "l"(p));
    return a;
}
__device__ __forceinline__ void ldsm4(uint32_t* r, uint32_t addr) {
    asm volatile("ldmatrix.sync.aligned.m8n8.x4.shared.b16 {%0,%1,%2,%3}, [%4];"
                 : "=r"(r[0]), "=r"(r[1]), "=r"(r[2]), "=r"(r[3]) : "r"(addr));
}
#define CP_ASYNC16(s, g) \
    asm volatile("cp.async.cg.shared.global [%0], [%1], 16;" :: "r"(s), "l"(g))
#define CP_COMMIT() asm volatile("cp.async.commit_group;" ::: "memory")
#define CP_WAIT1()  asm volatile("cp.async.wait_group 1;"  ::: "memory")

#define MMA_TF32(d, a, b) \
    asm volatile( \
        "mma.sync.aligned.m16n8k8.row.col.f32.tf32.tf32.f32 " \
        "{%0,%1,%2,%3}, {%4,%5,%6,%7}, {%8,%9}, {%0,%1,%2,%3};" \
        : "+f"((d)[0]), "+f"((d)[1]), "+f"((d)[2]), "+f"((d)[3]) \
        : "r"((a)[0]), "r"((a)[1]), "r"((a)[2]), "r"((a)[3]), \
          "r"((b)[0]), "r"((b)[1]))

#define SW(o) ((o) ^ (((o) >> 3) & 0x70))

#define TM 128
#define TN 128
#define TK 32
#define NSTAGE 3
#define STAGE_BYTES 32768
#define GEMM_SMEM (NSTAGE * STAGE_BYTES + 1024)

// ---------------------------------------------------------------------------
// tf32 mma.sync GEMM:  C = scale * (A @ B^T) + bias  [+ optional tf32 round]
// A: [M x K] row-major, B: [N x K] row-major; BOTH ALREADY tf32-ROUNDED.
// Compile-time leading dims / K.
// ldmatrix addressing: UNswizzled base + plain adds, constant XOR mask at the
// load (swizzle mask = row bits 0-2 << 4, a per-thread constant; all deltas
// are carry-free in the column field, so XOR-late == full swizzle).
// 256 threads = 8 warps (2m x 4n), warp tile 64x32, 3-stage cp.async
// pipeline + per-ks fragment double buffering.
// ---------------------------------------------------------------------------
template<int LDA, int LDB, int LDC, int K, bool HASBIAS, bool ROUND>
__global__ void __launch_bounds__(256, 2)
gemm_mma(const float* __restrict__ A, const float* __restrict__ B,
         const float* __restrict__ bias, float* __restrict__ C,
         long sA, long sB, long sC, long sBias, float scale)
{
    extern __shared__ char smraw[];
    const uint32_t sbase = (smem_u32(smraw) + 1023u) & ~1023u;

    const int tid = threadIdx.x;
    const int wid = tid >> 5;
    const int lid = tid & 31;
    const int g   = lid >> 2;
    const int t   = lid & 3;

    const int bz = blockIdx.z;
    A += (long)bz * sA;  B += (long)bz * sB;  C += (long)bz * sC;
    const int bm = blockIdx.y * TM;
    const int bn = blockIdx.x * TN;

    const int wm = (wid >> 2) * 64;
    const int wn = (wid & 3) * 32;

    // ldmatrix lane address components
    const int aRowL = lid & 15;
    const int akh   = lid >> 4;
    const int bRowL = (lid & 7) + ((lid >> 4) & 1) * 8;
    const int bkh   = (lid >> 3) & 1;

    // cp.async assignment: 4 x 16B per operand per chunk per thread
    const int ldr  = tid >> 3;
    const int lc16 = tid & 7;

    // per-thread gmem base pointers and constant (swizzled) smem store offset
    const float* aP = A + (long)(bm + ldr) * LDA + lc16 * 4;
    const float* bP = B + (long)(bn + ldr) * LDB + lc16 * 4;
    const uint32_t so0 = SW((ldr << 7) + (lc16 << 4));   // +u*4096 is carry-free

    // ldmatrix: UNswizzled bases + constant XOR masks (row bits 0-2 << 4)
    const uint32_t aU0   = sbase + ((wm + aRowL) << 7) + (akh << 4);
    const uint32_t bU0   = sbase + 16384 + ((wn + bRowL) << 7) + (bkh << 4);
    const uint32_t maskA = (uint32_t)(aRowL & 7) << 4;
    const uint32_t maskB = (uint32_t)(lid & 7) << 4;

    float acc[4][4][4];
#pragma unroll
    for (int i = 0; i < 4; i++)
#pragma unroll
        for (int j = 0; j < 4; j++)
#pragma unroll
            for (int r = 0; r < 4; r++) acc[i][j][r] = 0.f;

    const int nc = K / TK;

    auto issue = [&](int c) {
        const uint32_t As = sbase + (c % NSTAGE) * STAGE_BYTES + so0;
        const float* a = aP + c * TK;
        const float* b = bP + c * TK;
#pragma unroll
        for (int u = 0; u < 4; u++) {
            CP_ASYNC16(As + u * 4096,         a + u * 32 * LDA);
            CP_ASYNC16(As + 16384 + u * 4096, b + u * 32 * LDB);
        }
    };

    uint32_t af[2][4][4], bf[2][2][4];
    auto ldfrag = [&](uint32_t stoff, int ks, int buf) {
#pragma unroll
        for (int mi = 0; mi < 4; mi++)
            ldsm4(af[buf][mi], (aU0 + stoff + mi * 2048 + ks * 32) ^ maskA);
#pragma unroll
        for (int nb = 0; nb < 2; nb++)
            ldsm4(bf[buf][nb], (bU0 + stoff + nb * 2048 + ks * 32) ^ maskB);
    };

    issue(0); CP_COMMIT();
    issue(1); CP_COMMIT();

    for (int c = 0; c < nc; c++) {
        CP_WAIT1();
        __syncthreads();

        const uint32_t stoff = (c % NSTAGE) * STAGE_BYTES;

        ldfrag(stoff, 0, 0);           // warm first ks while we issue cp.async
        if (c + 2 < nc) issue(c + 2);
        CP_COMMIT();

#pragma unroll
        for (int ks = 0; ks < 4; ks++) {
            if (ks < 3) ldfrag(stoff, ks + 1, (ks + 1) & 1);
            const int cur = ks & 1;
#pragma unroll
            for (int mi = 0; mi < 4; mi++)
#pragma unroll
                for (int ni = 0; ni < 4; ni++)
                    MMA_TF32(acc[mi][ni], af[cur][mi], &bf[cur][ni >> 1][(ni & 1) * 2]);
        }
    }

    // ---- epilogue ----
    if (HASBIAS) bias += (long)bz * sBias;
#pragma unroll
    for (int mi = 0; mi < 4; mi++) {
        const int row0 = bm + wm + mi * 16 + g;
#pragma unroll
        for (int ni = 0; ni < 4; ni++) {
            const int col = bn + wn + ni * 8 + 2 * t;
            float bx = 0.f, by = 0.f;
            if (HASBIAS) { bx = bias[col]; by = bias[col + 1]; }
            float2 v0, v1;
            v0.x = acc[mi][ni][0] * scale + bx;
            v0.y = acc[mi][ni][1] * scale + by;
            v1.x = acc[mi][ni][2] * scale + bx;
            v1.y = acc[mi][ni][3] * scale + by;
            if (ROUND) {
                v0.x = tf32round(v0.x); v0.y = tf32round(v0.y);
                v1.x = tf32round(v1.x); v1.y = tf32round(v1.y);
            }
            *(float2*)(C + (long)row0 * LDC + col)       = v0;
            *(float2*)(C + (long)(row0 + 8) * LDC + col) = v1;
        }
    }
}

// ---------------------------------------------------------------------------
// Single prepass: round x -> Xr, Wq/Wk/Wv -> Wr slots, pack biases.
// ---------------------------------------------------------------------------
__global__ __launch_bounds__(256) void prep_kernel(
    const float4* __restrict__ x,
    const float4* __restrict__ wq, const float4* __restrict__ wk,
    const float4* __restrict__ wv,
    const float4* __restrict__ bq, const float4* __restrict__ bk,
    const float4* __restrict__ bv,
    float4* __restrict__ xr, float4* __restrict__ wr, float4* __restrict__ bdst,
    int xN4, int wN4)
{
    const int i = blockIdx.x * blockDim.x + threadIdx.x;
    auto rnd = [](float4 v) {
        v.x = tf32round(v.x); v.y = tf32round(v.y);
        v.z = tf32round(v.z); v.w = tf32round(v.w);
        return v;
    };
    if (i < xN4) {
        xr[i] = rnd(x[i]);
    } else {
        int j = i - xN4;
        if (j < 3 * wN4) {
            const int s = j / wN4, o = j - s * wN4;
            const float4* src = (s == 0) ? wq : (s == 1) ? wk : wv;
            wr[s * wN4 + o] = rnd(src[o]);
        } else {
            int k = j - 3 * wN4;
            if (k < 3 * (DIM / 4)) {
                const int s = k / (DIM / 4), o = k - s * (DIM / 4);
                const float4* src = (s == 0) ? bq : (s == 1) ? bk : bv;
                bdst[s * (DIM / 4) + o] = src[o];
            }
        }
    }
}

// ---------------------------------------------------------------------------
__global__ __launch_bounds__(256) void transpose_kernel(
    const float* __restrict__ V, float* __restrict__ Vt)
{
    __shared__ float t[32][33];
    const int b  = blockIdx.z;
    const int s0 = blockIdx.x * 32;
    const int d0 = blockIdx.y * 32;
#pragma unroll
    for (int i = threadIdx.y; i < 32; i += 8)
        t[i][threadIdx.x] = V[((long)b * SEQ + s0 + i) * DIM + d0 + threadIdx.x];
    __syncthreads();
#pragma unroll
    for (int i = threadIdx.y; i < 32; i += 8)
        Vt[((long)b * DIM + d0 + i) * SEQ + s0 + threadIdx.x] = t[threadIdx.x][i];
}

// ---------------------------------------------------------------------------
// Row-wise masked softmax (key axis). 2048 = 256 thr * 2 float4.
// ---------------------------------------------------------------------------
__global__ __launch_bounds__(256) void softmax_kernel(
    float* __restrict__ S, const int* __restrict__ mask)
{
    const int row = blockIdx.x;
    const int b   = row / SEQ;
    float4* s = (float4*)(S + (size_t)row * SEQ);
    const int4* m = (const int4*)(mask + b * SEQ);

    const int i0 = threadIdx.x;
    const int i1 = threadIdx.x + 256;

    float4 v0 = s[i0], v1 = s[i1];
    const int4 m0 = m[i0], m1 = m[i1];
    if (m0.x == 0) v0.x = -1e9f;
    if (m0.y == 0) v0.y = -1e9f;
    if (m0.z == 0) v0.z = -1e9f;
    if (m0.w == 0) v0.w = -1e9f;
    if (m1.x == 0) v1.x = -1e9f;
    if (m1.y == 0) v1.y = -1e9f;
    if (m1.z == 0) v1.z = -1e9f;
    if (m1.w == 0) v1.w = -1e9f;

    float mx = fmaxf(fmaxf(fmaxf(v0.x, v0.y), fmaxf(v0.z, v0.w)),
                     fmaxf(fmaxf(v1.x, v1.y), fmaxf(v1.z, v1.w)));
    __shared__ float red[8];
#pragma unroll
    for (int o = 16; o > 0; o >>= 1)
        mx = fmaxf(mx, __shfl_xor_sync(0xFFFFFFFF, mx, o));
    if ((threadIdx.x & 31) == 0) red[threadIdx.x >> 5] = mx;
    __syncthreads();
    {
        float r = red[threadIdx.x & 7];
#pragma unroll
        for (int o = 4; o > 0; o >>= 1)
            r = fmaxf(r, __shfl_xor_sync(0xFFFFFFFF, r, o));
        mx = r;
    }

    v0.x = __expf(v0.x - mx); v0.y = __expf(v0.y - mx);
    v0.z = __expf(v0.z - mx); v0.w = __expf(v0.w - mx);
    v1.x = __expf(v1.x - mx); v1.y = __expf(v1.y - mx);
    v1.z = __expf(v1.z - mx); v1.w = __expf(v1.w - mx);

    float sum = v0.x + v0.y + v0.z + v0.w + v1.x + v1.y + v1.z + v1.w;
#pragma unroll
    for (int o = 16; o > 0; o >>= 1)
        sum += __shfl_xor_sync(0xFFFFFFFF, sum, o);
    __syncthreads();
    if ((threadIdx.x & 31) == 0) red[threadIdx.x >> 5] = sum;
    __syncthreads();
    {
        float r = red[threadIdx.x & 7];
#pragma unroll
        for (int o = 4; o > 0; o >>= 1)
            r += __shfl_xor_sync(0xFFFFFFFF, r, o);
        sum = r;
    }

    const float inv = 1.f / sum;
    v0.x = tf32round(v0.x * inv); v0.y = tf32round(v0.y * inv);
    v0.z = tf32round(v0.z * inv); v0.w = tf32round(v0.w * inv);
    v1.x = tf32round(v1.x * inv); v1.y = tf32round(v1.y * inv);
    v1.z = tf32round(v1.z * inv); v1.w = tf32round(v1.w * inv);
    s[i0] = v0; s[i1] = v1;
}

// ---------------------------------------------------------------------------
extern "C" void kernel_launch(void* const* d_in, const int* in_sizes, int n_in,
                              void* d_out, int out_size)
{
    const float* x    = (const float*)d_in[0];
    const int*   mask = (const int*)  d_in[1];
    const float* Wk   = (const float*)d_in[2];
    const float* bk   = (const float*)d_in[3];
    const float* Wq   = (const float*)d_in[4];
    const float* bq   = (const float*)d_in[5];
    const float* Wv   = (const float*)d_in[6];
    const float* bv   = (const float*)d_in[7];
    float* out = (float*)d_out;

    float *QKV, *Vt, *S, *Xr, *Wr, *bias;
    cudaGetSymbolAddress((void**)&QKV,  g_QKV);
    cudaGetSymbolAddress((void**)&Vt,   g_Vt);
    cudaGetSymbolAddress((void**)&S,    g_S);
    cudaGetSymbolAddress((void**)&Xr,   g_Xr);
    cudaGetSymbolAddress((void**)&Wr,   g_Wr);
    cudaGetSymbolAddress((void**)&bias, g_b);

    const size_t PLANE = (size_t)BB * SEQ * DIM;
    float* Q  = QKV;
    float* Kp = QKV + PLANE;
    float* V  = QKV + 2 * PLANE;

    auto projK = gemm_mma<DIM, DIM, DIM,  DIM, true,  true >;
    auto scorK = gemm_mma<DIM, DIM, SEQ,  DIM, false, false>;
    auto avK   = gemm_mma<SEQ, SEQ, DIM,  SEQ, false, false>;
    cudaFuncSetAttribute(projK, cudaFuncAttributeMaxDynamicSharedMemorySize, GEMM_SMEM);
    cudaFuncSetAttribute(scorK, cudaFuncAttributeMaxDynamicSharedMemorySize, GEMM_SMEM);
    cudaFuncSetAttribute(avK,   cudaFuncAttributeMaxDynamicSharedMemorySize, GEMM_SMEM);

    // single prepass launch
    const int xN4 = BB * SEQ * DIM / 4;
    const int wN4 = DIM * DIM / 4;
    const int tot = xN4 + 3 * wN4 + 3 * (DIM / 4);
    prep_kernel<<<(tot + 255) / 256, 256>>>(
        (const float4*)x,
        (const float4*)Wq, (const float4*)Wk, (const float4*)Wv,
        (const float4*)bq, (const float4*)bk, (const float4*)bv,
        (float4*)Xr, (float4*)Wr, (float4*)bias, xN4, wN4);

    // merged QKV projection: grid.z selects (W, bias, output plane)
    dim3 gp(DIM / TN, (BB * SEQ) / TM, 3);
    projK<<<gp, 256, GEMM_SMEM>>>(Xr, Wr, bias, QKV,
                                  0, (long)DIM * DIM, (long)PLANE, DIM, 1.f);

    transpose_kernel<<<dim3(SEQ / 32, DIM / 32, BB), dim3(32, 8)>>>(V, Vt);

    // scores: S[b] = Q[b] @ K[b]^T / sqrt(D)
    const float inv_sqrt_d = 0.044194173824159216f;
    dim3 gs(SEQ / TN, SEQ / TM, BB);
    scorK<<<gs, 256, GEMM_SMEM>>>(Q, Kp, nullptr, S,
                                  (long)SEQ * DIM, (long)SEQ * DIM, (long)SEQ * SEQ, 0,
                                  inv_sqrt_d);

    softmax_kernel<<<BB * SEQ, 256>>>(S, mask);

    // out[b] = P[b] @ Vt[b]^T
    dim3 ga(DIM / TN, SEQ / TM, BB);
    avK<<<ga, 256, GEMM_SMEM>>>(S, Vt, nullptr, out,
                                (long)SEQ * SEQ, (long)SEQ * DIM, (long)SEQ * DIM, 0,
                                1.f);
}

// round 12
// speedup vs baseline: 4.2567x; 1.0386x over previous
#include <cuda_runtime.h>
#include <cstdint>

#define BB   8
#define SEQ  2048
#define DIM  512

// Scratch (device globals; no allocs allowed)
__device__ float g_QKV  [3 * (size_t)BB * SEQ * DIM];  // Q | K | V
__device__ float g_Vt   [(size_t)BB * SEQ * DIM];
__device__ float g_S    [(size_t)BB * SEQ * SEQ];      // scores -> P (exp'd)
__device__ float g_Xr   [(size_t)BB * SEQ * DIM];      // tf32-rounded x
__device__ float g_Wr   [3 * (size_t)DIM * DIM];       // tf32-rounded Wq|Wk|Wv
__device__ float g_b    [3 * DIM];                     // packed bq|bk|bv
__device__ float g_Spart[16 * (size_t)BB * SEQ];       // per-coltile row sums
__device__ float g_rsum [(size_t)BB * SEQ];            // full row sums

__device__ __forceinline__ uint32_t tf32cvt(float f) {
    uint32_t r; asm("cvt.rna.tf32.f32 %0, %1;" : "=r"(r) : "f"(f)); return r;
}
__device__ __forceinline__ float tf32round(float f) {
    return __uint_as_float(tf32cvt(f));
}
__device__ __forceinline__ uint32_t smem_u32(const void* p) {
    uint32_t a;
    asm("{ .reg .u64 t; cvta.to.shared.u64 t, %1; cvt.u32.u64 %0, t; }" : "=r"(a) : "l"(p));
    return a;
}
__device__ __forceinline__ void ldsm4(uint32_t* r, uint32_t addr) {
    asm volatile("ldmatrix.sync.aligned.m8n8.x4.shared.b16 {%0,%1,%2,%3}, [%4];"
                 : "=r"(r[0]), "=r"(r[1]), "=r"(r[2]), "=r"(r[3]) : "r"(addr));
}
#define CP_ASYNC16(s, g) \
    asm volatile("cp.async.cg.shared.global [%0], [%1], 16;" :: "r"(s), "l"(g))
#define CP_COMMIT() asm volatile("cp.async.commit_group;" ::: "memory")
#define CP_WAIT1()  asm volatile("cp.async.wait_group 1;"  ::: "memory")

#define MMA_TF32(d, a, b) \
    asm volatile( \
        "mma.sync.aligned.m16n8k8.row.col.f32.tf32.tf32.f32 " \
        "{%0,%1,%2,%3}, {%4,%5,%6,%7}, {%8,%9}, {%0,%1,%2,%3};" \
        : "+f"((d)[0]), "+f"((d)[1]), "+f"((d)[2]), "+f"((d)[3]) \
        : "r"((a)[0]), "r"((a)[1]), "r"((a)[2]), "r"((a)[3]), \
          "r"((b)[0]), "r"((b)[1]))

#define SW(o) ((o) ^ (((o) >> 3) & 0x70))

#define TM 128
#define TN 128
#define TK 32
#define NSTAGE 3
#define STAGE_BYTES 32768
#define GEMM_SMEM (NSTAGE * STAGE_BYTES + 1024)

// Epilogue modes
#define EPI_PROJ 0   // +bias, tf32-round outputs
#define EPI_SOFT 1   // exp(scale*s) with mask, tf32-round, partial row sums
#define EPI_AV   2   // divide rows by rsum (softmax normalization)

// ---------------------------------------------------------------------------
// tf32 mma.sync GEMM:  C = epi( A @ B^T )
// A: [M x K] row-major, B: [N x K] row-major; BOTH ALREADY tf32-ROUNDED.
// 256 threads = 8 warps (2m x 4n), warp tile 64x32, ldmatrix fragments
// (unswizzled base + constant XOR mask), 3-stage cp.async pipeline,
// per-ks fragment double buffering.
// ---------------------------------------------------------------------------
template<int LDA, int LDB, int LDC, int K, int EPI>
__global__ void __launch_bounds__(256, 2)
gemm_mma(const float* __restrict__ A, const float* __restrict__ B,
         float* __restrict__ C,
         const float* __restrict__ bias, const int* __restrict__ mask,
         float* __restrict__ spart, const float* __restrict__ rsum,
         long sA, long sB, long sC, float scale)
{
    extern __shared__ char smraw[];
    const uint32_t sbase = (smem_u32(smraw) + 1023u) & ~1023u;

    const int tid = threadIdx.x;
    const int wid = tid >> 5;
    const int lid = tid & 31;
    const int g   = lid >> 2;
    const int t   = lid & 3;

    const int bz = blockIdx.z;
    A += (long)bz * sA;  B += (long)bz * sB;  C += (long)bz * sC;
    const int bm = blockIdx.y * TM;
    const int bn = blockIdx.x * TN;

    const int wm = (wid >> 2) * 64;
    const int wn = (wid & 3) * 32;

    const int aRowL = lid & 15;
    const int akh   = lid >> 4;
    const int bRowL = (lid & 7) + ((lid >> 4) & 1) * 8;
    const int bkh   = (lid >> 3) & 1;

    const int ldr  = tid >> 3;
    const int lc16 = tid & 7;

    const float* aP = A + (long)(bm + ldr) * LDA + lc16 * 4;
    const float* bP = B + (long)(bn + ldr) * LDB + lc16 * 4;
    const uint32_t so0 = SW((ldr << 7) + (lc16 << 4));   // +u*4096 carry-free

    const uint32_t aU0   = sbase + ((wm + aRowL) << 7) + (akh << 4);
    const uint32_t bU0   = sbase + 16384 + ((wn + bRowL) << 7) + (bkh << 4);
    const uint32_t maskA = (uint32_t)(aRowL & 7) << 4;
    const uint32_t maskB = (uint32_t)(lid & 7) << 4;

    float acc[4][4][4];
#pragma unroll
    for (int i = 0; i < 4; i++)
#pragma unroll
        for (int j = 0; j < 4; j++)
#pragma unroll
            for (int r = 0; r < 4; r++) acc[i][j][r] = 0.f;

    const int nc = K / TK;

    auto issue = [&](int c) {
        const uint32_t As = sbase + (c % NSTAGE) * STAGE_BYTES + so0;
        const float* a = aP + c * TK;
        const float* b = bP + c * TK;
#pragma unroll
        for (int u = 0; u < 4; u++) {
            CP_ASYNC16(As + u * 4096,         a + u * 32 * LDA);
            CP_ASYNC16(As + 16384 + u * 4096, b + u * 32 * LDB);
        }
    };

    uint32_t af[2][4][4], bf[2][2][4];
    auto ldfrag = [&](uint32_t stoff, int ks, int buf) {
#pragma unroll
        for (int mi = 0; mi < 4; mi++)
            ldsm4(af[buf][mi], (aU0 + stoff + mi * 2048 + ks * 32) ^ maskA);
#pragma unroll
        for (int nb = 0; nb < 2; nb++)
            ldsm4(bf[buf][nb], (bU0 + stoff + nb * 2048 + ks * 32) ^ maskB);
    };

    issue(0); CP_COMMIT();
    issue(1); CP_COMMIT();

    for (int c = 0; c < nc; c++) {
        CP_WAIT1();
        __syncthreads();

        const uint32_t stoff = (c % NSTAGE) * STAGE_BYTES;

        ldfrag(stoff, 0, 0);
        if (c + 2 < nc) issue(c + 2);
        CP_COMMIT();

#pragma unroll
        for (int ks = 0; ks < 4; ks++) {
            if (ks < 3) ldfrag(stoff, ks + 1, (ks + 1) & 1);
            const int cur = ks & 1;
#pragma unroll
            for (int mi = 0; mi < 4; mi++)
#pragma unroll
                for (int ni = 0; ni < 4; ni++)
                    MMA_TF32(acc[mi][ni], af[cur][mi], &bf[cur][ni >> 1][(ni & 1) * 2]);
        }
    }

    // ======================= epilogues =======================
    if (EPI == EPI_PROJ) {
        bias += (long)bz * DIM;
#pragma unroll
        for (int mi = 0; mi < 4; mi++) {
            const int row0 = bm + wm + mi * 16 + g;
#pragma unroll
            for (int ni = 0; ni < 4; ni++) {
                const int col = bn + wn + ni * 8 + 2 * t;
                const float bx = bias[col], by = bias[col + 1];
                float2 v0, v1;
                v0.x = tf32round(acc[mi][ni][0] + bx);
                v0.y = tf32round(acc[mi][ni][1] + by);
                v1.x = tf32round(acc[mi][ni][2] + bx);
                v1.y = tf32round(acc[mi][ni][3] + by);
                *(float2*)(C + (long)row0 * LDC + col)       = v0;
                *(float2*)(C + (long)(row0 + 8) * LDC + col) = v1;
            }
        }
    } else if (EPI == EPI_SOFT) {
        // exp + mask + write P; accumulate this CTA's 128-col partial row sums
        mask += (long)bz * SEQ;
        __syncthreads();                       // smem stages -> scratch reuse
        float* part = (float*)smraw;           // [4][128] floats
        const int wnidx = wid & 3;
#pragma unroll
        for (int mi = 0; mi < 4; mi++) {
            const int rloc = wm + mi * 16 + g; // 0..127
            const int row0 = bm + rloc;
            float s0 = 0.f, s8 = 0.f;
#pragma unroll
            for (int ni = 0; ni < 4; ni++) {
                const int col = bn + wn + ni * 8 + 2 * t;
                const int m0 = mask[col], m1 = mask[col + 1];
                float e0 = m0 ? tf32round(__expf(acc[mi][ni][0] * scale)) : 0.f;
                float e1 = m1 ? tf32round(__expf(acc[mi][ni][1] * scale)) : 0.f;
                float e2 = m0 ? tf32round(__expf(acc[mi][ni][2] * scale)) : 0.f;
                float e3 = m1 ? tf32round(__expf(acc[mi][ni][3] * scale)) : 0.f;
                *(float2*)(C + (long)row0 * LDC + col)       = make_float2(e0, e1);
                *(float2*)(C + (long)(row0 + 8) * LDC + col) = make_float2(e2, e3);
                s0 += e0 + e1;
                s8 += e2 + e3;
            }
            // reduce across the 4 t-lanes of each quad
            s0 += __shfl_xor_sync(0xFFFFFFFF, s0, 1);
            s0 += __shfl_xor_sync(0xFFFFFFFF, s0, 2);
            s8 += __shfl_xor_sync(0xFFFFFFFF, s8, 1);
            s8 += __shfl_xor_sync(0xFFFFFFFF, s8, 2);
            if (t == 0) {
                part[wnidx * 128 + rloc]     = s0;
                part[wnidx * 128 + rloc + 8] = s8;
            }
        }
        __syncthreads();
        if (tid < 128) {
            const float r = part[tid] + part[128 + tid] + part[256 + tid] + part[384 + tid];
            spart[(long)blockIdx.x * (BB * SEQ) + (long)bz * SEQ + bm + tid] = r;
        }
    } else { // EPI_AV
        rsum += (long)bz * SEQ;
#pragma unroll
        for (int mi = 0; mi < 4; mi++) {
            const int row0 = bm + wm + mi * 16 + g;
            const float inv0 = 1.f / rsum[row0];
            const float inv8 = 1.f / rsum[row0 + 8];
#pragma unroll
            for (int ni = 0; ni < 4; ni++) {
                const int col = bn + wn + ni * 8 + 2 * t;
                float2 v0, v1;
                v0.x = acc[mi][ni][0] * inv0;
                v0.y = acc[mi][ni][1] * inv0;
                v1.x = acc[mi][ni][2] * inv8;
                v1.y = acc[mi][ni][3] * inv8;
                *(float2*)(C + (long)row0 * LDC + col)       = v0;
                *(float2*)(C + (long)(row0 + 8) * LDC + col) = v1;
            }
        }
    }
}

// ---------------------------------------------------------------------------
// Fold 16 per-coltile partial sums -> full row sums. Deterministic.
// ---------------------------------------------------------------------------
__global__ __launch_bounds__(256) void rowsum_kernel(
    const float* __restrict__ spart, float* __restrict__ rsum)
{
    const int r = blockIdx.x * blockDim.x + threadIdx.x;   // 0 .. BB*SEQ-1
    float s = 0.f;
#pragma unroll
    for (int t = 0; t < 16; t++)
        s += spart[(long)t * (BB * SEQ) + r];
    rsum[r] = s;
}

// ---------------------------------------------------------------------------
// Single prepass: round x -> Xr, Wq/Wk/Wv -> Wr slots, pack biases.
// ---------------------------------------------------------------------------
__global__ __launch_bounds__(256) void prep_kernel(
    const float4* __restrict__ x,
    const float4* __restrict__ wq, const float4* __restrict__ wk,
    const float4* __restrict__ wv,
    const float4* __restrict__ bq, const float4* __restrict__ bk,
    const float4* __restrict__ bv,
    float4* __restrict__ xr, float4* __restrict__ wr, float4* __restrict__ bdst,
    int xN4, int wN4)
{
    const int i = blockIdx.x * blockDim.x + threadIdx.x;
    auto rnd = [](float4 v) {
        v.x = tf32round(v.x); v.y = tf32round(v.y);
        v.z = tf32round(v.z); v.w = tf32round(v.w);
        return v;
    };
    if (i < xN4) {
        xr[i] = rnd(x[i]);
    } else {
        int j = i - xN4;
        if (j < 3 * wN4) {
            const int s = j / wN4, o = j - s * wN4;
            const float4* src = (s == 0) ? wq : (s == 1) ? wk : wv;
            wr[s * wN4 + o] = rnd(src[o]);
        } else {
            int k = j - 3 * wN4;
            if (k < 3 * (DIM / 4)) {
                const int s = k / (DIM / 4), o = k - s * (DIM / 4);
                const float4* src = (s == 0) ? bq : (s == 1) ? bk : bv;
                bdst[s * (DIM / 4) + o] = src[o];
            }
        }
    }
}

// ---------------------------------------------------------------------------
__global__ __launch_bounds__(256) void transpose_kernel(
    const float* __restrict__ V, float* __restrict__ Vt)
{
    __shared__ float t[32][33];
    const int b  = blockIdx.z;
    const int s0 = blockIdx.x * 32;
    const int d0 = blockIdx.y * 32;
#pragma unroll
    for (int i = threadIdx.y; i < 32; i += 8)
        t[i][threadIdx.x] = V[((long)b * SEQ + s0 + i) * DIM + d0 + threadIdx.x];
    __syncthreads();
#pragma unroll
    for (int i = threadIdx.y; i < 32; i += 8)
        Vt[((long)b * DIM + d0 + i) * SEQ + s0 + threadIdx.x] = t[threadIdx.x][i];
}

// ---------------------------------------------------------------------------
extern "C" void kernel_launch(void* const* d_in, const int* in_sizes, int n_in,
                              void* d_out, int out_size)
{
    const float* x    = (const float*)d_in[0];
    const int*   mask = (const int*)  d_in[1];
    const float* Wk   = (const float*)d_in[2];
    const float* bk   = (const float*)d_in[3];
    const float* Wq   = (const float*)d_in[4];
    const float* bq   = (const float*)d_in[5];
    const float* Wv   = (const float*)d_in[6];
    const float* bv   = (const float*)d_in[7];
    float* out = (float*)d_out;

    float *QKV, *Vt, *S, *Xr, *Wr, *bias, *Spart, *rsum;
    cudaGetSymbolAddress((void**)&QKV,   g_QKV);
    cudaGetSymbolAddress((void**)&Vt,    g_Vt);
    cudaGetSymbolAddress((void**)&S,     g_S);
    cudaGetSymbolAddress((void**)&Xr,    g_Xr);
    cudaGetSymbolAddress((void**)&Wr,    g_Wr);
    cudaGetSymbolAddress((void**)&bias,  g_b);
    cudaGetSymbolAddress((void**)&Spart, g_Spart);
    cudaGetSymbolAddress((void**)&rsum,  g_rsum);

    const size_t PLANE = (size_t)BB * SEQ * DIM;
    float* Q  = QKV;
    float* Kp = QKV + PLANE;
    float* V  = QKV + 2 * PLANE;

    auto projK = gemm_mma<DIM, DIM, DIM, DIM, EPI_PROJ>;
    auto scorK = gemm_mma<DIM, DIM, SEQ, DIM, EPI_SOFT>;
    auto avK   = gemm_mma<SEQ, SEQ, DIM, SEQ, EPI_AV>;
    cudaFuncSetAttribute(projK, cudaFuncAttributeMaxDynamicSharedMemorySize, GEMM_SMEM);
    cudaFuncSetAttribute(scorK, cudaFuncAttributeMaxDynamicSharedMemorySize, GEMM_SMEM);
    cudaFuncSetAttribute(avK,   cudaFuncAttributeMaxDynamicSharedMemorySize, GEMM_SMEM);

    // single prepass launch
    const int xN4 = BB * SEQ * DIM / 4;
    const int wN4 = DIM * DIM / 4;
    const int tot = xN4 + 3 * wN4 + 3 * (DIM / 4);
    prep_kernel<<<(tot + 255) / 256, 256>>>(
        (const float4*)x,
        (const float4*)Wq, (const float4*)Wk, (const float4*)Wv,
        (const float4*)bq, (const float4*)bk, (const float4*)bv,
        (float4*)Xr, (float4*)Wr, (float4*)bias, xN4, wN4);

    // merged QKV projection: grid.z selects (W, bias, output plane)
    dim3 gp(DIM / TN, (BB * SEQ) / TM, 3);
    projK<<<gp, 256, GEMM_SMEM>>>(Xr, Wr, QKV, bias, nullptr, nullptr, nullptr,
                                  0, (long)DIM * DIM, (long)PLANE, 1.f);

    transpose_kernel<<<dim3(SEQ / 32, DIM / 32, BB), dim3(32, 8)>>>(V, Vt);

    // scores + masked exp + partial row sums:  P[b] = exp(Q K^T / sqrt(D))
    const float inv_sqrt_d = 0.044194173824159216f;
    dim3 gs(SEQ / TN, SEQ / TM, BB);
    scorK<<<gs, 256, GEMM_SMEM>>>(Q, Kp, S, nullptr, mask, Spart, nullptr,
                                  (long)SEQ * DIM, (long)SEQ * DIM, (long)SEQ * SEQ,
                                  inv_sqrt_d);

    // fold partial sums
    rowsum_kernel<<<(BB * SEQ) / 256, 256>>>(Spart, rsum);

    // out[b] = (P[b] @ Vt[b]^T) / rowsum
    dim3 ga(DIM / TN, SEQ / TM, BB);
    avK<<<ga, 256, GEMM_SMEM>>>(S, Vt, out, nullptr, nullptr, nullptr, rsum,
                                (long)SEQ * SEQ, (long)SEQ * DIM, (long)SEQ * DIM,
                                1.f);
}

// round 13
// speedup vs baseline: 4.2968x; 1.0094x over previous
#include <cuda_runtime.h>
#include <cstdint>

#define BB   8
#define SEQ  2048
#define DIM  512

// Scratch (device globals; no allocs allowed)
__device__ float g_QK   [2 * (size_t)BB * SEQ * DIM];  // Q | K
__device__ float g_Vt   [(size_t)BB * SEQ * DIM];      // V transposed [b][d][s]
__device__ float g_S    [(size_t)BB * SEQ * SEQ];      // scores -> P (exp'd)
__device__ float g_Xr   [(size_t)BB * SEQ * DIM];      // tf32-rounded x
__device__ float g_Wr   [3 * (size_t)DIM * DIM];       // tf32-rounded Wq|Wk|Wv
__device__ float g_b    [3 * DIM];                     // packed bq|bk|bv
__device__ float g_Spart[16 * (size_t)BB * SEQ];       // per-coltile row sums
__device__ float g_rsum [(size_t)BB * SEQ];            // full row sums

__device__ __forceinline__ uint32_t tf32cvt(float f) {
    uint32_t r; asm("cvt.rna.tf32.f32 %0, %1;" : "=r"(r) : "f"(f)); return r;
}
__device__ __forceinline__ float tf32round(float f) {
    return __uint_as_float(tf32cvt(f));
}
__device__ __forceinline__ uint32_t smem_u32(const void* p) {
    uint32_t a;
    asm("{ .reg .u64 t; cvta.to.shared.u64 t, %1; cvt.u32.u64 %0, t; }" : "=r"(a) : "l"(p));
    return a;
}
__device__ __forceinline__ void ldsm4(uint32_t* r, uint32_t addr) {
    asm volatile("ldmatrix.sync.aligned.m8n8.x4.shared.b16 {%0,%1,%2,%3}, [%4];"
                 : "=r"(r[0]), "=r"(r[1]), "=r"(r[2]), "=r"(r[3]) : "r"(addr));
}
#define CP_ASYNC16(s, g) \
    asm volatile("cp.async.cg.shared.global [%0], [%1], 16;" :: "r"(s), "l"(g))
#define CP_COMMIT() asm volatile("cp.async.commit_group;" ::: "memory")
#define CP_WAIT1()  asm volatile("cp.async.wait_group 1;"  ::: "memory")

#define MMA_TF32(d, a, b) \
    asm volatile( \
        "mma.sync.aligned.m16n8k8.row.col.f32.tf32.tf32.f32 " \
        "{%0,%1,%2,%3}, {%4,%5,%6,%7}, {%8,%9}, {%0,%1,%2,%3};" \
        : "+f"((d)[0]), "+f"((d)[1]), "+f"((d)[2]), "+f"((d)[3]) \
        : "r"((a)[0]), "r"((a)[1]), "r"((a)[2]), "r"((a)[3]), \
          "r"((b)[0]), "r"((b)[1]))

#define SW(o) ((o) ^ (((o) >> 3) & 0x70))

#define TM 128
#define TN 128
#define TK 32
#define NSTAGE 3
#define STAGE_BYTES 32768
#define GEMM_SMEM (NSTAGE * STAGE_BYTES + 1024)

// Epilogue modes
#define EPI_PROJ  0   // +bias[col], tf32-round
#define EPI_SOFT  1   // exp(scale*s) with mask, tf32-round, partial row sums
#define EPI_AV    2   // divide rows by rsum
#define EPI_PROJT 3   // +bias[row], tf32-round (transposed projection)

// ---------------------------------------------------------------------------
// tf32 mma.sync GEMM:  C = epi( A @ B^T )
// A: [M x K] row-major, B: [N x K] row-major; BOTH ALREADY tf32-ROUNDED.
// 256 threads = 8 warps (2m x 4n), warp tile 64x32, ldmatrix fragments
// (unswizzled base + constant XOR mask), 3-stage cp.async pipeline,
// per-ks fragment double buffering.
// ---------------------------------------------------------------------------
template<int LDA, int LDB, int LDC, int K, int EPI>
__global__ void __launch_bounds__(256, 2)
gemm_mma(const float* __restrict__ A, const float* __restrict__ B,
         float* __restrict__ C,
         const float* __restrict__ bias, const int* __restrict__ mask,
         float* __restrict__ spart, const float* __restrict__ rsum,
         long sA, long sB, long sC, float scale)
{
    extern __shared__ char smraw[];
    const uint32_t sbase = (smem_u32(smraw) + 1023u) & ~1023u;

    const int tid = threadIdx.x;
    const int wid = tid >> 5;
    const int lid = tid & 31;
    const int g   = lid >> 2;
    const int t   = lid & 3;

    const int bz = blockIdx.z;
    A += (long)bz * sA;  B += (long)bz * sB;  C += (long)bz * sC;
    const int bm = blockIdx.y * TM;
    const int bn = blockIdx.x * TN;

    const int wm = (wid >> 2) * 64;
    const int wn = (wid & 3) * 32;

    const int aRowL = lid & 15;
    const int akh   = lid >> 4;
    const int bRowL = (lid & 7) + ((lid >> 4) & 1) * 8;
    const int bkh   = (lid >> 3) & 1;

    const int ldr  = tid >> 3;
    const int lc16 = tid & 7;

    const float* aP = A + (long)(bm + ldr) * LDA + lc16 * 4;
    const float* bP = B + (long)(bn + ldr) * LDB + lc16 * 4;
    const uint32_t so0 = SW((ldr << 7) + (lc16 << 4));   // +u*4096 carry-free

    const uint32_t aU0   = sbase + ((wm + aRowL) << 7) + (akh << 4);
    const uint32_t bU0   = sbase + 16384 + ((wn + bRowL) << 7) + (bkh << 4);
    const uint32_t maskA = (uint32_t)(aRowL & 7) << 4;
    const uint32_t maskB = (uint32_t)(lid & 7) << 4;

    float acc[4][4][4];
#pragma unroll
    for (int i = 0; i < 4; i++)
#pragma unroll
        for (int j = 0; j < 4; j++)
#pragma unroll
            for (int r = 0; r < 4; r++) acc[i][j][r] = 0.f;

    const int nc = K / TK;

    auto issue = [&](int c) {
        const uint32_t As = sbase + (c % NSTAGE) * STAGE_BYTES + so0;
        const float* a = aP + c * TK;
        const float* b = bP + c * TK;
#pragma unroll
        for (int u = 0; u < 4; u++) {
            CP_ASYNC16(As + u * 4096,         a + u * 32 * LDA);
            CP_ASYNC16(As + 16384 + u * 4096, b + u * 32 * LDB);
        }
    };

    uint32_t af[2][4][4], bf[2][2][4];
    auto ldfrag = [&](uint32_t stoff, int ks, int buf) {
#pragma unroll
        for (int mi = 0; mi < 4; mi++)
            ldsm4(af[buf][mi], (aU0 + stoff + mi * 2048 + ks * 32) ^ maskA);
#pragma unroll
        for (int nb = 0; nb < 2; nb++)
            ldsm4(bf[buf][nb], (bU0 + stoff + nb * 2048 + ks * 32) ^ maskB);
    };

    issue(0); CP_COMMIT();
    issue(1); CP_COMMIT();

    for (int c = 0; c < nc; c++) {
        CP_WAIT1();
        __syncthreads();

        const uint32_t stoff = (c % NSTAGE) * STAGE_BYTES;

        ldfrag(stoff, 0, 0);
        if (c + 2 < nc) issue(c + 2);
        CP_COMMIT();

#pragma unroll
        for (int ks = 0; ks < 4; ks++) {
            if (ks < 3) ldfrag(stoff, ks + 1, (ks + 1) & 1);
            const int cur = ks & 1;
#pragma unroll
            for (int mi = 0; mi < 4; mi++)
#pragma unroll
                for (int ni = 0; ni < 4; ni++)
                    MMA_TF32(acc[mi][ni], af[cur][mi], &bf[cur][ni >> 1][(ni & 1) * 2]);
        }
    }

    // ======================= epilogues =======================
    if (EPI == EPI_PROJ) {
        bias += (long)bz * DIM;
#pragma unroll
        for (int mi = 0; mi < 4; mi++) {
            const int row0 = bm + wm + mi * 16 + g;
#pragma unroll
            for (int ni = 0; ni < 4; ni++) {
                const int col = bn + wn + ni * 8 + 2 * t;
                const float bx = bias[col], by = bias[col + 1];
                float2 v0, v1;
                v0.x = tf32round(acc[mi][ni][0] + bx);
                v0.y = tf32round(acc[mi][ni][1] + by);
                v1.x = tf32round(acc[mi][ni][2] + bx);
                v1.y = tf32round(acc[mi][ni][3] + by);
                *(float2*)(C + (long)row0 * LDC + col)       = v0;
                *(float2*)(C + (long)(row0 + 8) * LDC + col) = v1;
            }
        }
    } else if (EPI == EPI_PROJT) {
        // row-indexed bias (C rows are output features)
#pragma unroll
        for (int mi = 0; mi < 4; mi++) {
            const int row0 = bm + wm + mi * 16 + g;
            const float b0 = bias[row0];
            const float b8 = bias[row0 + 8];
#pragma unroll
            for (int ni = 0; ni < 4; ni++) {
                const int col = bn + wn + ni * 8 + 2 * t;
                float2 v0, v1;
                v0.x = tf32round(acc[mi][ni][0] + b0);
                v0.y = tf32round(acc[mi][ni][1] + b0);
                v1.x = tf32round(acc[mi][ni][2] + b8);
                v1.y = tf32round(acc[mi][ni][3] + b8);
                *(float2*)(C + (long)row0 * LDC + col)       = v0;
                *(float2*)(C + (long)(row0 + 8) * LDC + col) = v1;
            }
        }
    } else if (EPI == EPI_SOFT) {
        // exp + mask + write P; accumulate this CTA's 128-col partial row sums
        mask += (long)bz * SEQ;
        int mk[8];
#pragma unroll
        for (int ni = 0; ni < 4; ni++) {
            const int col = bn + wn + ni * 8 + 2 * t;
            mk[ni * 2]     = mask[col];
            mk[ni * 2 + 1] = mask[col + 1];
        }
        __syncthreads();                       // smem stages -> scratch reuse
        float* part = (float*)smraw;           // [4][128] floats
        const int wnidx = wid & 3;
#pragma unroll
        for (int mi = 0; mi < 4; mi++) {
            const int rloc = wm + mi * 16 + g; // 0..127
            const int row0 = bm + rloc;
            float s0 = 0.f, s8 = 0.f;
#pragma unroll
            for (int ni = 0; ni < 4; ni++) {
                const int col = bn + wn + ni * 8 + 2 * t;
                float e0 = mk[ni * 2]     ? tf32round(__expf(acc[mi][ni][0] * scale)) : 0.f;
                float e1 = mk[ni * 2 + 1] ? tf32round(__expf(acc[mi][ni][1] * scale)) : 0.f;
                float e2 = mk[ni * 2]     ? tf32round(__expf(acc[mi][ni][2] * scale)) : 0.f;
                float e3 = mk[ni * 2 + 1] ? tf32round(__expf(acc[mi][ni][3] * scale)) : 0.f;
                *(float2*)(C + (long)row0 * LDC + col)       = make_float2(e0, e1);
                *(float2*)(C + (long)(row0 + 8) * LDC + col) = make_float2(e2, e3);
                s0 += e0 + e1;
                s8 += e2 + e3;
            }
            s0 += __shfl_xor_sync(0xFFFFFFFF, s0, 1);
            s0 += __shfl_xor_sync(0xFFFFFFFF, s0, 2);
            s8 += __shfl_xor_sync(0xFFFFFFFF, s8, 1);
            s8 += __shfl_xor_sync(0xFFFFFFFF, s8, 2);
            if (t == 0) {
                part[wnidx * 128 + rloc]     = s0;
                part[wnidx * 128 + rloc + 8] = s8;
            }
        }
        __syncthreads();
        if (tid < 128) {
            const float r = part[tid] + part[128 + tid] + part[256 + tid] + part[384 + tid];
            spart[(long)blockIdx.x * (BB * SEQ) + (long)bz * SEQ + bm + tid] = r;
        }
    } else { // EPI_AV
        rsum += (long)bz * SEQ;
#pragma unroll
        for (int mi = 0; mi < 4; mi++) {
            const int row0 = bm + wm + mi * 16 + g;
            const float inv0 = 1.f / rsum[row0];
            const float inv8 = 1.f / rsum[row0 + 8];
#pragma unroll
            for (int ni = 0; ni < 4; ni++) {
                const int col = bn + wn + ni * 8 + 2 * t;
                float2 v0, v1;
                v0.x = acc[mi][ni][0] * inv0;
                v0.y = acc[mi][ni][1] * inv0;
                v1.x = acc[mi][ni][2] * inv8;
                v1.y = acc[mi][ni][3] * inv8;
                *(float2*)(C + (long)row0 * LDC + col)       = v0;
                *(float2*)(C + (long)(row0 + 8) * LDC + col) = v1;
            }
        }
    }
}

// ---------------------------------------------------------------------------
// Fold 16 per-coltile partial sums -> full row sums. Deterministic.
// ---------------------------------------------------------------------------
__global__ __launch_bounds__(256) void rowsum_kernel(
    const float* __restrict__ spart, float* __restrict__ rsum)
{
    const int r = blockIdx.x * blockDim.x + threadIdx.x;
    float s = 0.f;
#pragma unroll
    for (int t = 0; t < 16; t++)
        s += spart[(long)t * (BB * SEQ) + r];
    rsum[r] = s;
}

// ---------------------------------------------------------------------------
// Single prepass: round x -> Xr, Wq/Wk/Wv -> Wr slots, pack biases.
// ---------------------------------------------------------------------------
__global__ __launch_bounds__(256) void prep_kernel(
    const float4* __restrict__ x,
    const float4* __restrict__ wq, const float4* __restrict__ wk,
    const float4* __restrict__ wv,
    const float4* __restrict__ bq, const float4* __restrict__ bk,
    const float4* __restrict__ bv,
    float4* __restrict__ xr, float4* __restrict__ wr, float4* __restrict__ bdst,
    int xN4, int wN4)
{
    const int i = blockIdx.x * blockDim.x + threadIdx.x;
    auto rnd = [](float4 v) {
        v.x = tf32round(v.x); v.y = tf32round(v.y);
        v.z = tf32round(v.z); v.w = tf32round(v.w);
        return v;
    };
    if (i < xN4) {
        xr[i] = rnd(x[i]);
    } else {
        int j = i - xN4;
        if (j < 3 * wN4) {
            const int s = j / wN4, o = j - s * wN4;
            const float4* src = (s == 0) ? wq : (s == 1) ? wk : wv;
            wr[s * wN4 + o] = rnd(src[o]);
        } else {
            int k = j - 3 * wN4;
            if (k < 3 * (DIM / 4)) {
                const int s = k / (DIM / 4), o = k - s * (DIM / 4);
                const float4* src = (s == 0) ? bq : (s == 1) ? bk : bv;
                bdst[s * (DIM / 4) + o] = src[o];
            }
        }
    }
}

// ---------------------------------------------------------------------------
extern "C" void kernel_launch(void* const* d_in, const int* in_sizes, int n_in,
                              void* d_out, int out_size)
{
    const float* x    = (const float*)d_in[0];
    const int*   mask = (const int*)  d_in[1];
    const float* Wk   = (const float*)d_in[2];
    const float* bk   = (const float*)d_in[3];
    const float* Wq   = (const float*)d_in[4];
    const float* bq   = (const float*)d_in[5];
    const float* Wv   = (const float*)d_in[6];
    const float* bv   = (const float*)d_in[7];
    float* out = (float*)d_out;

    float *QK, *Vt, *S, *Xr, *Wr, *bias, *Spart, *rsum;
    cudaGetSymbolAddress((void**)&QK,    g_QK);
    cudaGetSymbolAddress((void**)&Vt,    g_Vt);
    cudaGetSymbolAddress((void**)&S,     g_S);
    cudaGetSymbolAddress((void**)&Xr,    g_Xr);
    cudaGetSymbolAddress((void**)&Wr,    g_Wr);
    cudaGetSymbolAddress((void**)&bias,  g_b);
    cudaGetSymbolAddress((void**)&Spart, g_Spart);
    cudaGetSymbolAddress((void**)&rsum,  g_rsum);

    const size_t PLANE = (size_t)BB * SEQ * DIM;
    float* Q  = QK;
    float* Kp = QK + PLANE;

    auto projK  = gemm_mma<DIM, DIM, DIM, DIM, EPI_PROJ>;
    auto projTK = gemm_mma<DIM, DIM, SEQ, DIM, EPI_PROJT>;
    auto scorK  = gemm_mma<DIM, DIM, SEQ, DIM, EPI_SOFT>;
    auto avK    = gemm_mma<SEQ, SEQ, DIM, SEQ, EPI_AV>;
    cudaFuncSetAttribute(projK,  cudaFuncAttributeMaxDynamicSharedMemorySize, GEMM_SMEM);
    cudaFuncSetAttribute(projTK, cudaFuncAttributeMaxDynamicSharedMemorySize, GEMM_SMEM);
    cudaFuncSetAttribute(scorK,  cudaFuncAttributeMaxDynamicSharedMemorySize, GEMM_SMEM);
    cudaFuncSetAttribute(avK,    cudaFuncAttributeMaxDynamicSharedMemorySize, GEMM_SMEM);

    // single prepass launch (Wr slots: 0=Wq, 1=Wk, 2=Wv; bias: bq|bk|bv)
    const int xN4 = BB * SEQ * DIM / 4;
    const int wN4 = DIM * DIM / 4;
    const int tot = xN4 + 3 * wN4 + 3 * (DIM / 4);
    prep_kernel<<<(tot + 255) / 256, 256>>>(
        (const float4*)x,
        (const float4*)Wq, (const float4*)Wk, (const float4*)Wv,
        (const float4*)bq, (const float4*)bk, (const float4*)bv,
        (float4*)Xr, (float4*)Wr, (float4*)bias, xN4, wN4);

    // Q/K projections: grid.z in {0,1} selects (W, bias, output plane)
    dim3 gp(DIM / TN, (BB * SEQ) / TM, 2);
    projK<<<gp, 256, GEMM_SMEM>>>(Xr, Wr, QK, bias, nullptr, nullptr, nullptr,
                                  0, (long)DIM * DIM, (long)PLANE, 1.f);

    // Vt projection, directly transposed: Vt[b] = Wv @ Xr[b]^T + bv (row bias)
    dim3 gt(SEQ / TN, DIM / TM, BB);
    projTK<<<gt, 256, GEMM_SMEM>>>(Wr + 2L * DIM * DIM, Xr, Vt,
                                   bias + 2L * DIM, nullptr, nullptr, nullptr,
                                   0, (long)SEQ * DIM, (long)SEQ * DIM, 1.f);

    // scores + masked exp + partial row sums:  P[b] = exp(Q K^T / sqrt(D))
    const float inv_sqrt_d = 0.044194173824159216f;
    dim3 gs(SEQ / TN, SEQ / TM, BB);
    scorK<<<gs, 256, GEMM_SMEM>>>(Q, Kp, S, nullptr, mask, Spart, nullptr,
                                  (long)SEQ * DIM, (long)SEQ * DIM, (long)SEQ * SEQ,
                                  inv_sqrt_d);

    // fold partial sums
    rowsum_kernel<<<(BB * SEQ) / 256, 256>>>(Spart, rsum);

    // out[b] = (P[b] @ Vt[b]^T) / rowsum
    dim3 ga(DIM / TN, SEQ / TM, BB);
    avK<<<ga, 256, GEMM_SMEM>>>(S, Vt, out, nullptr, nullptr, nullptr, rsum,
                                (long)SEQ * SEQ, (long)SEQ * DIM, (long)SEQ * DIM,
                                1.f);
}